// round 8
// baseline (speedup 1.0000x reference)
#include <cuda_runtime.h>
#include <cuda_bf16.h>
#include <math.h>
#include <stdint.h>

#define NN 50000
#define NE 800000
#define FH 192          // HEADS*HID
#define HID 64
#define LOG2E 1.4426950408889634f

// ---------------- scratch (static device globals; no allocation) ----------------
__device__ __align__(16) float g_feat[NN * FH];   // 38.4 MB
__device__ __align__(16) __nv_bfloat16 g_Ahi[NN * 128];
__device__ __align__(16) __nv_bfloat16 g_Alo[NN * 128];
#define BW_TOT (192*128 + 4*192*64)
__device__ __align__(16) __nv_bfloat16 g_Bhi5[BW_TOT];
__device__ __align__(16) __nv_bfloat16 g_Blo5[BW_TOT];
__device__ __align__(16) float4 g_el4[NN];
__device__ __align__(16) float4 g_er4[NN];
__device__ int   g_cnt[NN];
__device__ int   g_rp[NN + 1];
__device__ int   g_wp[NN];
__device__ int   g_col[NE];
__device__ int   g_bsum[64];

__device__ __forceinline__ float lrelu(float x, float s) { return x > 0.f ? x : s * x; }

// ---------------- CSR build ----------------
__global__ void k_zero() {
    int i = blockIdx.x * blockDim.x + threadIdx.x;
    if (i < NN) g_cnt[i] = 0;
}
__global__ void k_hist(const int* __restrict__ dst) {
    int e = blockIdx.x * blockDim.x + threadIdx.x;
    if (e < NE) atomicAdd(&g_cnt[dst[e]], 1);
}
__global__ __launch_bounds__(1024) void k_scanA() {
    __shared__ int wsum[32];
    int tid = threadIdx.x, lane = tid & 31, wid = tid >> 5;
    int i = blockIdx.x * 1024 + tid;
    int v = (i < NN) ? g_cnt[i] : 0;
    int x = v;
    #pragma unroll
    for (int o = 1; o < 32; o <<= 1) {
        int t = __shfl_up_sync(0xffffffffu, x, o);
        if (lane >= o) x += t;
    }
    if (lane == 31) wsum[wid] = x;
    __syncthreads();
    if (wid == 0) {
        int y = wsum[lane];
        #pragma unroll
        for (int o = 1; o < 32; o <<= 1) {
            int t = __shfl_up_sync(0xffffffffu, y, o);
            if (lane >= o) y += t;
        }
        wsum[lane] = y;
    }
    __syncthreads();
    int pre = (wid ? wsum[wid - 1] : 0) + x - v;
    if (i < NN) g_rp[i] = pre;
    if (tid == 1023) g_bsum[blockIdx.x] = pre + v;
}
__global__ __launch_bounds__(1024) void k_scanB(int nblk) {
    __shared__ int sb[64];
    int tid = threadIdx.x;
    if (tid < nblk) sb[tid] = g_bsum[tid];
    __syncthreads();
    int off = 0;
    for (int j = 0; j < (int)blockIdx.x; j++) off += sb[j];
    int i = blockIdx.x * 1024 + tid;
    if (i < NN) {
        int v = g_rp[i] + off;
        g_rp[i] = v;
        g_wp[i] = v;
    }
    if (blockIdx.x == gridDim.x - 1 && tid == 0) {
        int tot = 0;
        for (int j = 0; j < nblk; j++) tot += sb[j];
        g_rp[NN] = tot;
    }
}
__global__ void k_scatter(const int* __restrict__ src, const int* __restrict__ dst) {
    int e = blockIdx.x * blockDim.x + threadIdx.x;
    if (e < NE) {
        int p = atomicAdd(&g_wp[dst[e]], 1);
        g_col[p] = src[e];
    }
}

// ---------------- zero attention accumulators ----------------
__global__ void k_zero_el() {
    int i = blockIdx.x * blockDim.x + threadIdx.x;
    if (i < NN) {
        g_el4[i] = make_float4(0.f, 0.f, 0.f, 0.f);
        g_er4[i] = make_float4(0.f, 0.f, 0.f, 0.f);
    }
}

// ---------------- bf16 hi/lo splits ----------------
__global__ void k_splitA(const float* __restrict__ src, int n4) {
    int i = blockIdx.x * blockDim.x + threadIdx.x;
    if (i < n4) {
        float4 v = *(const float4*)(src + 4 * i);
        __nv_bfloat16 h0 = __float2bfloat16(v.x), h1 = __float2bfloat16(v.y);
        __nv_bfloat16 h2 = __float2bfloat16(v.z), h3 = __float2bfloat16(v.w);
        ((__nv_bfloat162*)g_Ahi)[2 * i]     = __nv_bfloat162(h0, h1);
        ((__nv_bfloat162*)g_Ahi)[2 * i + 1] = __nv_bfloat162(h2, h3);
        ((__nv_bfloat162*)g_Alo)[2 * i] = __nv_bfloat162(
            __float2bfloat16(v.x - __bfloat162float(h0)),
            __float2bfloat16(v.y - __bfloat162float(h1)));
        ((__nv_bfloat162*)g_Alo)[2 * i + 1] = __nv_bfloat162(
            __float2bfloat16(v.z - __bfloat162float(h2)),
            __float2bfloat16(v.w - __bfloat162float(h3)));
    }
}
__global__ void k_splitW_all(const float* __restrict__ W0, const float* __restrict__ W1,
                             const float* __restrict__ W2, const float* __restrict__ W3,
                             const float* __restrict__ W4) {
    int i = blockIdx.x * blockDim.x + threadIdx.x;
    if (i >= BW_TOT) return;
    int l, j, K, off;
    if (i < 192 * 128) { l = 0; j = i; K = 128; off = 0; }
    else {
        int r = i - 192 * 128;
        l = 1 + r / (192 * 64);
        j = r % (192 * 64);
        K = 64;
        off = 192 * 128 + (l - 1) * 192 * 64;
    }
    const float* W = (l == 0) ? W0 : (l == 1) ? W1 : (l == 2) ? W2 : (l == 3) ? W3 : W4;
    int k = j / FH, n = j % FH;
    float v = W[j];
    __nv_bfloat16 h = __float2bfloat16(v);
    g_Bhi5[off + n * K + k] = h;
    g_Blo5[off + n * K + k] = __float2bfloat16(v - __bfloat162float(h));
}

// ---------------- mma.sync bf16 split GEMM + fused attention-logit epilogue ----------------
__device__ __forceinline__ void mma16816(float* d, const uint32_t* a, const uint32_t* b) {
    asm volatile("mma.sync.aligned.m16n8k16.row.col.f32.bf16.bf16.f32 "
        "{%0,%1,%2,%3}, {%4,%5,%6,%7}, {%8,%9}, {%0,%1,%2,%3};"
        : "+f"(d[0]), "+f"(d[1]), "+f"(d[2]), "+f"(d[3])
        : "r"(a[0]), "r"(a[1]), "r"(a[2]), "r"(a[3]), "r"(b[0]), "r"(b[1]));
}
#define ASTR 24

template <int K>
__global__ __launch_bounds__(256) void k_gemm_mma(int boff, const float* __restrict__ al,
                                                  const float* __restrict__ ar) {
    __shared__ __nv_bfloat16 As[2][128 * ASTR];
    __shared__ __nv_bfloat16 Bs[2][96 * ASTR];
    int tid = threadIdx.x, lane = tid & 31, w = tid >> 5;
    int mw = w & 3, nw = w >> 2;
    int m0 = blockIdx.x * 128, n0 = blockIdx.y * 96;
    int g = lane >> 2, t = lane & 3;

    float d[2][6][4];
    #pragma unroll
    for (int i = 0; i < 2; i++)
        #pragma unroll
        for (int j = 0; j < 6; j++)
            #pragma unroll
            for (int q = 0; q < 4; q++) d[i][j][q] = 0.f;

    for (int k0 = 0; k0 < K; k0 += 16) {
        {
            int r = tid >> 1, p = tid & 1;
            #pragma unroll
            for (int half = 0; half < 2; half++) {
                const __nv_bfloat16* src = half ? g_Alo : g_Ahi;
                uint4 v = make_uint4(0u, 0u, 0u, 0u);
                if (m0 + r < NN)
                    v = *(const uint4*)(src + (size_t)(m0 + r) * K + k0 + p * 8);
                *(uint4*)(&As[half][r * ASTR + p * 8]) = v;
            }
        }
        if (tid < 192) {
            int r = tid >> 1, p = tid & 1;
            #pragma unroll
            for (int half = 0; half < 2; half++) {
                const __nv_bfloat16* src = (half ? g_Blo5 : g_Bhi5) + boff;
                uint4 v = *(const uint4*)(src + (n0 + r) * K + k0 + p * 8);
                *(uint4*)(&Bs[half][r * ASTR + p * 8]) = v;
            }
        }
        __syncthreads();

        uint32_t afr[2][2][4];
        #pragma unroll
        for (int half = 0; half < 2; half++)
            #pragma unroll
            for (int mt = 0; mt < 2; mt++) {
                const __nv_bfloat16* base = &As[half][(mw * 32 + mt * 16) * ASTR];
                afr[half][mt][0] = *(const uint32_t*)(base + g * ASTR + 2 * t);
                afr[half][mt][1] = *(const uint32_t*)(base + (g + 8) * ASTR + 2 * t);
                afr[half][mt][2] = *(const uint32_t*)(base + g * ASTR + 2 * t + 8);
                afr[half][mt][3] = *(const uint32_t*)(base + (g + 8) * ASTR + 2 * t + 8);
            }
        uint32_t bfr[2][6][2];
        #pragma unroll
        for (int half = 0; half < 2; half++)
            #pragma unroll
            for (int nt = 0; nt < 6; nt++) {
                const __nv_bfloat16* base = &Bs[half][(nw * 48 + nt * 8) * ASTR];
                bfr[half][nt][0] = *(const uint32_t*)(base + g * ASTR + 2 * t);
                bfr[half][nt][1] = *(const uint32_t*)(base + g * ASTR + 2 * t + 8);
            }
        #pragma unroll
        for (int mt = 0; mt < 2; mt++)
            #pragma unroll
            for (int nt = 0; nt < 6; nt++) {
                mma16816(d[mt][nt], afr[0][mt], bfr[0][nt]);
                mma16816(d[mt][nt], afr[0][mt], bfr[1][nt]);
                mma16816(d[mt][nt], afr[1][mt], bfr[0][nt]);
            }
        __syncthreads();
    }

    // store feat tile
    #pragma unroll
    for (int mt = 0; mt < 2; mt++) {
        int r0 = m0 + mw * 32 + mt * 16 + g;
        #pragma unroll
        for (int nt = 0; nt < 6; nt++) {
            int c = n0 + nw * 48 + nt * 8 + 2 * t;
            if (r0 < NN)
                *(float2*)&g_feat[(size_t)r0 * FH + c] = make_float2(d[mt][nt][0], d[mt][nt][1]);
            if (r0 + 8 < NN)
                *(float2*)&g_feat[(size_t)(r0 + 8) * FH + c] = make_float2(d[mt][nt][2], d[mt][nt][3]);
        }
    }

    // fused attention logits: partial el/er for this thread's 48-col slice.
    // slice spans at most 2 heads: hA = n0q>>6, hB = (n0q+47)>>6.
    int n0q = n0 + nw * 48;
    int hA = n0q >> 6, hB = (n0q + 47) >> 6;
    float pelA[2][2] = {{0.f, 0.f}, {0.f, 0.f}}, pelB[2][2] = {{0.f, 0.f}, {0.f, 0.f}};
    float perA[2][2] = {{0.f, 0.f}, {0.f, 0.f}}, perB[2][2] = {{0.f, 0.f}, {0.f, 0.f}};
    #pragma unroll
    for (int nt = 0; nt < 6; nt++) {
        int c = n0q + nt * 8 + 2 * t;
        float a0 = al[c] * LOG2E, a1 = al[c + 1] * LOG2E;
        float r0v = ar[c] * LOG2E, r1v = ar[c + 1] * LOG2E;
        bool isA = ((n0q + nt * 8) >> 6) == hA;
        #pragma unroll
        for (int mt = 0; mt < 2; mt++) {
            float el_g  = d[mt][nt][0] * a0 + d[mt][nt][1] * a1;
            float el_g8 = d[mt][nt][2] * a0 + d[mt][nt][3] * a1;
            float er_g  = d[mt][nt][0] * r0v + d[mt][nt][1] * r1v;
            float er_g8 = d[mt][nt][2] * r0v + d[mt][nt][3] * r1v;
            if (isA) {
                pelA[mt][0] += el_g;  pelA[mt][1] += el_g8;
                perA[mt][0] += er_g;  perA[mt][1] += er_g8;
            } else {
                pelB[mt][0] += el_g;  pelB[mt][1] += el_g8;
                perB[mt][0] += er_g;  perB[mt][1] += er_g8;
            }
        }
    }
    // reduce across the 4 t-lanes of each quad
    #pragma unroll
    for (int mt = 0; mt < 2; mt++)
        #pragma unroll
        for (int gg = 0; gg < 2; gg++) {
            #pragma unroll
            for (int o = 1; o <= 2; o <<= 1) {
                pelA[mt][gg] += __shfl_xor_sync(0xffffffffu, pelA[mt][gg], o);
                pelB[mt][gg] += __shfl_xor_sync(0xffffffffu, pelB[mt][gg], o);
                perA[mt][gg] += __shfl_xor_sync(0xffffffffu, perA[mt][gg], o);
                perB[mt][gg] += __shfl_xor_sync(0xffffffffu, perB[mt][gg], o);
            }
        }
    if (t == 0) {
        #pragma unroll
        for (int mt = 0; mt < 2; mt++) {
            #pragma unroll
            for (int gg = 0; gg < 2; gg++) {
                int r = m0 + mw * 32 + mt * 16 + g + gg * 8;
                if (r < NN) {
                    atomicAdd(((float*)&g_el4[r]) + hA, pelA[mt][gg]);
                    atomicAdd(((float*)&g_er4[r]) + hA, perA[mt][gg]);
                    if (hB != hA) {
                        atomicAdd(((float*)&g_el4[r]) + hB, pelB[mt][gg]);
                        atomicAdd(((float*)&g_er4[r]) + hB, perB[mt][gg]);
                    }
                }
            }
        }
    }
}

// ---------------- single-pass online-softmax aggregation, x2 unrolled ----------------
__global__ __launch_bounds__(256) void k_agg(const float* __restrict__ b,
                                             const float* __restrict__ Wo,
                                             const float* __restrict__ bo,
                                             float* __restrict__ out) {
    int w = (blockIdx.x * blockDim.x + threadIdx.x) >> 5;
    int lane = threadIdx.x & 31;
    if (w >= NN) return;
    int beg = g_rp[w], end = g_rp[w + 1];
    float4 er = g_er4[w];

    float m0 = -1e30f, m1 = -1e30f, m2 = -1e30f;
    float s0 = 0.f, s1 = 0.f, s2 = 0.f;
    float2 a0 = {0.f, 0.f}, a1 = {0.f, 0.f}, a2 = {0.f, 0.f};

    int e = beg;
    for (; e + 1 < end; e += 2) {
        int sA = g_col[e], sB = g_col[e + 1];
        float4 eA = g_el4[sA];
        float4 eB = g_el4[sB];
        const float2* fA = (const float2*)(g_feat + (size_t)sA * FH);
        const float2* fB = (const float2*)(g_feat + (size_t)sB * FH);
        float2 vA0 = fA[lane], vA1 = fA[lane + 32], vA2 = fA[lane + 64];
        float2 vB0 = fB[lane], vB1 = fB[lane + 32], vB2 = fB[lane + 64];
        float xA0 = lrelu(eA.x + er.x, 0.2f), xB0 = lrelu(eB.x + er.x, 0.2f);
        float xA1 = lrelu(eA.y + er.y, 0.2f), xB1 = lrelu(eB.y + er.y, 0.2f);
        float xA2 = lrelu(eA.z + er.z, 0.2f), xB2 = lrelu(eB.z + er.z, 0.2f);
        float n0m = fmaxf(xA0, xB0), n1m = fmaxf(xA1, xB1), n2m = fmaxf(xA2, xB2);
        if (n0m > m0) { float sc = exp2f(m0 - n0m); s0 *= sc; a0.x *= sc; a0.y *= sc; m0 = n0m; }
        if (n1m > m1) { float sc = exp2f(m1 - n1m); s1 *= sc; a1.x *= sc; a1.y *= sc; m1 = n1m; }
        if (n2m > m2) { float sc = exp2f(m2 - n2m); s2 *= sc; a2.x *= sc; a2.y *= sc; m2 = n2m; }
        float wA0 = exp2f(xA0 - m0), wB0 = exp2f(xB0 - m0);
        float wA1 = exp2f(xA1 - m1), wB1 = exp2f(xB1 - m1);
        float wA2 = exp2f(xA2 - m2), wB2 = exp2f(xB2 - m2);
        s0 += wA0 + wB0; s1 += wA1 + wB1; s2 += wA2 + wB2;
        a0.x += wA0 * vA0.x + wB0 * vB0.x; a0.y += wA0 * vA0.y + wB0 * vB0.y;
        a1.x += wA1 * vA1.x + wB1 * vB1.x; a1.y += wA1 * vA1.y + wB1 * vB1.y;
        a2.x += wA2 * vA2.x + wB2 * vB2.x; a2.y += wA2 * vA2.y + wB2 * vB2.y;
    }
    if (e < end) {
        int s = g_col[e];
        float4 el = g_el4[s];
        const float2* f2 = (const float2*)(g_feat + (size_t)s * FH);
        float2 v0 = f2[lane], v1 = f2[lane + 32], v2 = f2[lane + 64];
        float x0 = lrelu(el.x + er.x, 0.2f);
        float x1 = lrelu(el.y + er.y, 0.2f);
        float x2 = lrelu(el.z + er.z, 0.2f);
        if (x0 > m0) { float sc = exp2f(m0 - x0); s0 *= sc; a0.x *= sc; a0.y *= sc; m0 = x0; }
        if (x1 > m1) { float sc = exp2f(m1 - x1); s1 *= sc; a1.x *= sc; a1.y *= sc; m1 = x1; }
        if (x2 > m2) { float sc = exp2f(m2 - x2); s2 *= sc; a2.x *= sc; a2.y *= sc; m2 = x2; }
        float w0 = exp2f(x0 - m0), w1 = exp2f(x1 - m1), w2 = exp2f(x2 - m2);
        s0 += w0; s1 += w1; s2 += w2;
        a0.x += w0 * v0.x; a0.y += w0 * v0.y;
        a1.x += w1 * v1.x; a1.y += w1 * v1.y;
        a2.x += w2 * v2.x; a2.y += w2 * v2.y;
    }
    float i0 = s0 > 0.f ? 1.f / s0 : 0.f;
    float i1 = s1 > 0.f ? 1.f / s1 : 0.f;
    float i2 = s2 > 0.f ? 1.f / s2 : 0.f;
    float2 b0 = *(const float2*)(b + 2 * lane);
    float2 b1 = *(const float2*)(b + 64 + 2 * lane);
    float2 b2 = *(const float2*)(b + 128 + 2 * lane);
    float v0x = lrelu(a0.x * i0 + b0.x, 0.01f), v0y = lrelu(a0.y * i0 + b0.y, 0.01f);
    float v1x = lrelu(a1.x * i1 + b1.x, 0.01f), v1y = lrelu(a1.y * i1 + b1.y, 0.01f);
    float v2x = lrelu(a2.x * i2 + b2.x, 0.01f), v2y = lrelu(a2.y * i2 + b2.y, 0.01f);
    float rx = (v0x + v1x + v2x) * (1.f / 3.f);
    float ry = (v0y + v1y + v2y) * (1.f / 3.f);

    if (Wo) {
        #pragma unroll
        for (int c = 0; c < 8; c++) {
            float v = rx * Wo[(2 * lane) * 8 + c] + ry * Wo[(2 * lane + 1) * 8 + c];
            #pragma unroll
            for (int o = 16; o; o >>= 1) v += __shfl_xor_sync(0xffffffffu, v, o);
            if (lane == 0) out[w * 8 + c] = v + bo[c];
        }
    } else {
        __nv_bfloat16 hx = __float2bfloat16(rx);
        __nv_bfloat16 hy = __float2bfloat16(ry);
        __nv_bfloat16 lx = __float2bfloat16(rx - __bfloat162float(hx));
        __nv_bfloat16 ly = __float2bfloat16(ry - __bfloat162float(hy));
        ((__nv_bfloat162*)g_Ahi)[w * 32 + lane] = __nv_bfloat162(hx, hy);
        ((__nv_bfloat162*)g_Alo)[w * 32 + lane] = __nv_bfloat162(lx, ly);
    }
}

// ---------------- launch ----------------
extern "C" void kernel_launch(void* const* d_in, const int* in_sizes, int n_in,
                              void* d_out, int out_size) {
    const float* x   = (const float*)d_in[0];
    const int*   src = (const int*)d_in[1];
    const int*   dst = (const int*)d_in[2];
    const float *W[5], *b[5], *al[5], *ar[5];
    for (int l = 0; l < 5; l++) {
        W[l]  = (const float*)d_in[3 + 4 * l];
        b[l]  = (const float*)d_in[4 + 4 * l];
        al[l] = (const float*)d_in[5 + 4 * l];
        ar[l] = (const float*)d_in[6 + 4 * l];
    }
    const float* Wo = (const float*)d_in[23];
    const float* bo = (const float*)d_in[24];
    float* out = (float*)d_out;

    int nblk = (NN + 1023) / 1024;
    k_zero<<<(NN + 255) / 256, 256>>>();
    k_hist<<<(NE + 255) / 256, 256>>>(dst);
    k_scanA<<<nblk, 1024>>>();
    k_scanB<<<nblk, 1024>>>(nblk);
    k_scatter<<<(NE + 255) / 256, 256>>>(src, dst);

    k_splitW_all<<<(BW_TOT + 255) / 256, 256>>>(W[0], W[1], W[2], W[3], W[4]);
    k_splitA<<<(NN * 32 + 255) / 256, 256>>>(x, NN * 32);

    int wgrid = (NN * 32 + 255) / 256;
    int ngrid = (NN + 255) / 256;
    dim3 ggrid((NN + 127) / 128, 2);
    for (int l = 0; l < 5; l++) {
        int boff = (l == 0) ? 0 : 192 * 128 + (l - 1) * 192 * 64;
        k_zero_el<<<ngrid, 256>>>();
        if (l == 0) k_gemm_mma<128><<<ggrid, 256>>>(boff, al[l], ar[l]);
        else        k_gemm_mma<64><<<ggrid, 256>>>(boff, al[l], ar[l]);
        if (l == 4) k_agg<<<wgrid, 256>>>(b[l], Wo, bo, out);
        else        k_agg<<<wgrid, 256>>>(b[l], nullptr, nullptr, nullptr);
    }
}

// round 9
// speedup vs baseline: 1.3053x; 1.3053x over previous
#include <cuda_runtime.h>
#include <cuda_bf16.h>
#include <math.h>
#include <stdint.h>

#define NN 50000
#define NE 800000
#define FH 192          // HEADS*HID
#define HID 64
#define LOG2E 1.4426950408889634f

// ---------------- scratch (static device globals; no allocation) ----------------
__device__ __align__(16) float g_feat[NN * FH];   // 38.4 MB
__device__ __align__(16) __nv_bfloat16 g_Ahi[NN * 128];
__device__ __align__(16) __nv_bfloat16 g_Alo[NN * 128];
#define BW_TOT (192*128 + 4*192*64)
__device__ __align__(16) __nv_bfloat16 g_Bhi5[BW_TOT];
__device__ __align__(16) __nv_bfloat16 g_Blo5[BW_TOT];
__device__ __align__(16) float4 g_el4[NN];
__device__ __align__(16) float4 g_er4[NN];
__device__ int   g_cnt[NN];
__device__ int   g_rp[NN + 1];
__device__ int   g_wp[NN];
__device__ int   g_col[NE];
__device__ int   g_bsum[64];

__device__ __forceinline__ float lrelu(float x, float s) { return x > 0.f ? x : s * x; }

// ---------------- CSR build ----------------
__global__ void k_zero() {
    int i = blockIdx.x * blockDim.x + threadIdx.x;
    if (i < NN) g_cnt[i] = 0;
}
__global__ void k_hist(const int* __restrict__ dst) {
    int e = blockIdx.x * blockDim.x + threadIdx.x;
    if (e < NE) atomicAdd(&g_cnt[dst[e]], 1);
}
__global__ __launch_bounds__(1024) void k_scanA() {
    __shared__ int wsum[32];
    int tid = threadIdx.x, lane = tid & 31, wid = tid >> 5;
    int i = blockIdx.x * 1024 + tid;
    int v = (i < NN) ? g_cnt[i] : 0;
    int x = v;
    #pragma unroll
    for (int o = 1; o < 32; o <<= 1) {
        int t = __shfl_up_sync(0xffffffffu, x, o);
        if (lane >= o) x += t;
    }
    if (lane == 31) wsum[wid] = x;
    __syncthreads();
    if (wid == 0) {
        int y = wsum[lane];
        #pragma unroll
        for (int o = 1; o < 32; o <<= 1) {
            int t = __shfl_up_sync(0xffffffffu, y, o);
            if (lane >= o) y += t;
        }
        wsum[lane] = y;
    }
    __syncthreads();
    int pre = (wid ? wsum[wid - 1] : 0) + x - v;
    if (i < NN) g_rp[i] = pre;
    if (tid == 1023) g_bsum[blockIdx.x] = pre + v;
}
__global__ __launch_bounds__(1024) void k_scanB(int nblk) {
    __shared__ int sb[64];
    int tid = threadIdx.x;
    if (tid < nblk) sb[tid] = g_bsum[tid];
    __syncthreads();
    int off = 0;
    for (int j = 0; j < (int)blockIdx.x; j++) off += sb[j];
    int i = blockIdx.x * 1024 + tid;
    if (i < NN) {
        int v = g_rp[i] + off;
        g_rp[i] = v;
        g_wp[i] = v;
    }
    if (blockIdx.x == gridDim.x - 1 && tid == 0) {
        int tot = 0;
        for (int j = 0; j < nblk; j++) tot += sb[j];
        g_rp[NN] = tot;
    }
}
__global__ void k_scatter(const int* __restrict__ src, const int* __restrict__ dst) {
    int e = blockIdx.x * blockDim.x + threadIdx.x;
    if (e < NE) {
        int p = atomicAdd(&g_wp[dst[e]], 1);
        g_col[p] = src[e];
    }
}

// ---------------- bf16 hi/lo splits ----------------
__global__ void k_splitA(const float* __restrict__ src, int n) {
    int i = blockIdx.x * blockDim.x + threadIdx.x;
    if (i < n) {
        float v = src[i];
        __nv_bfloat16 h = __float2bfloat16(v);
        g_Ahi[i] = h;
        g_Alo[i] = __float2bfloat16(v - __bfloat162float(h));
    }
}
__global__ void k_splitW_all(const float* __restrict__ W0, const float* __restrict__ W1,
                             const float* __restrict__ W2, const float* __restrict__ W3,
                             const float* __restrict__ W4) {
    int i = blockIdx.x * blockDim.x + threadIdx.x;
    if (i >= BW_TOT) return;
    int l, j, K, off;
    if (i < 192 * 128) { l = 0; j = i; K = 128; off = 0; }
    else {
        int r = i - 192 * 128;
        l = 1 + r / (192 * 64);
        j = r % (192 * 64);
        K = 64;
        off = 192 * 128 + (l - 1) * 192 * 64;
    }
    const float* W = (l == 0) ? W0 : (l == 1) ? W1 : (l == 2) ? W2 : (l == 3) ? W3 : W4;
    int k = j / FH, n = j % FH;
    float v = W[j];
    __nv_bfloat16 h = __float2bfloat16(v);
    g_Bhi5[off + n * K + k] = h;
    g_Blo5[off + n * K + k] = __float2bfloat16(v - __bfloat162float(h));
}

// ---------------- mma.sync bf16 split GEMM ----------------
__device__ __forceinline__ void mma16816(float* d, const uint32_t* a, const uint32_t* b) {
    asm volatile("mma.sync.aligned.m16n8k16.row.col.f32.bf16.bf16.f32 "
        "{%0,%1,%2,%3}, {%4,%5,%6,%7}, {%8,%9}, {%0,%1,%2,%3};"
        : "+f"(d[0]), "+f"(d[1]), "+f"(d[2]), "+f"(d[3])
        : "r"(a[0]), "r"(a[1]), "r"(a[2]), "r"(a[3]), "r"(b[0]), "r"(b[1]));
}
#define ASTR 24

template <int K>
__global__ __launch_bounds__(256) void k_gemm_mma(int boff) {
    __shared__ __nv_bfloat16 As[2][128 * ASTR];
    __shared__ __nv_bfloat16 Bs[2][96 * ASTR];
    int tid = threadIdx.x, lane = tid & 31, w = tid >> 5;
    int mw = w & 3, nw = w >> 2;
    int m0 = blockIdx.x * 128, n0 = blockIdx.y * 96;
    int g = lane >> 2, t = lane & 3;

    float d[2][6][4];
    #pragma unroll
    for (int i = 0; i < 2; i++)
        #pragma unroll
        for (int j = 0; j < 6; j++)
            #pragma unroll
            for (int q = 0; q < 4; q++) d[i][j][q] = 0.f;

    for (int k0 = 0; k0 < K; k0 += 16) {
        {
            int r = tid >> 1, p = tid & 1;
            #pragma unroll
            for (int half = 0; half < 2; half++) {
                const __nv_bfloat16* src = half ? g_Alo : g_Ahi;
                uint4 v = make_uint4(0u, 0u, 0u, 0u);
                if (m0 + r < NN)
                    v = *(const uint4*)(src + (size_t)(m0 + r) * K + k0 + p * 8);
                *(uint4*)(&As[half][r * ASTR + p * 8]) = v;
            }
        }
        if (tid < 192) {
            int r = tid >> 1, p = tid & 1;
            #pragma unroll
            for (int half = 0; half < 2; half++) {
                const __nv_bfloat16* src = (half ? g_Blo5 : g_Bhi5) + boff;
                uint4 v = *(const uint4*)(src + (n0 + r) * K + k0 + p * 8);
                *(uint4*)(&Bs[half][r * ASTR + p * 8]) = v;
            }
        }
        __syncthreads();

        uint32_t afr[2][2][4];
        #pragma unroll
        for (int half = 0; half < 2; half++)
            #pragma unroll
            for (int mt = 0; mt < 2; mt++) {
                const __nv_bfloat16* base = &As[half][(mw * 32 + mt * 16) * ASTR];
                afr[half][mt][0] = *(const uint32_t*)(base + g * ASTR + 2 * t);
                afr[half][mt][1] = *(const uint32_t*)(base + (g + 8) * ASTR + 2 * t);
                afr[half][mt][2] = *(const uint32_t*)(base + g * ASTR + 2 * t + 8);
                afr[half][mt][3] = *(const uint32_t*)(base + (g + 8) * ASTR + 2 * t + 8);
            }
        uint32_t bfr[2][6][2];
        #pragma unroll
        for (int half = 0; half < 2; half++)
            #pragma unroll
            for (int nt = 0; nt < 6; nt++) {
                const __nv_bfloat16* base = &Bs[half][(nw * 48 + nt * 8) * ASTR];
                bfr[half][nt][0] = *(const uint32_t*)(base + g * ASTR + 2 * t);
                bfr[half][nt][1] = *(const uint32_t*)(base + g * ASTR + 2 * t + 8);
            }
        #pragma unroll
        for (int mt = 0; mt < 2; mt++)
            #pragma unroll
            for (int nt = 0; nt < 6; nt++) {
                mma16816(d[mt][nt], afr[0][mt], bfr[0][nt]);
                mma16816(d[mt][nt], afr[0][mt], bfr[1][nt]);
                mma16816(d[mt][nt], afr[1][mt], bfr[0][nt]);
            }
        __syncthreads();
    }

    #pragma unroll
    for (int mt = 0; mt < 2; mt++) {
        int r0 = m0 + mw * 32 + mt * 16 + g;
        #pragma unroll
        for (int nt = 0; nt < 6; nt++) {
            int c = n0 + nw * 48 + nt * 8 + 2 * t;
            if (r0 < NN)
                *(float2*)&g_feat[(size_t)r0 * FH + c] = make_float2(d[mt][nt][0], d[mt][nt][1]);
            if (r0 + 8 < NN)
                *(float2*)&g_feat[(size_t)(r0 + 8) * FH + c] = make_float2(d[mt][nt][2], d[mt][nt][3]);
        }
    }
}

// ---------------- attention logits ----------------
__global__ void k_attn(const float* __restrict__ al, const float* __restrict__ ar) {
    int w = (blockIdx.x * blockDim.x + threadIdx.x) >> 5;
    int lane = threadIdx.x & 31;
    if (w >= NN) return;
    const float2* f2 = (const float2*)(g_feat + (size_t)w * FH);
    float pl[3], pr[3];
    #pragma unroll
    for (int h = 0; h < 3; h++) {
        float2 v = f2[h * 32 + lane];
        float2 a = *(const float2*)(al + h * 64 + 2 * lane);
        float2 r = *(const float2*)(ar + h * 64 + 2 * lane);
        pl[h] = v.x * a.x + v.y * a.y;
        pr[h] = v.x * r.x + v.y * r.y;
    }
    #pragma unroll
    for (int h = 0; h < 3; h++) {
        #pragma unroll
        for (int o = 16; o; o >>= 1) {
            pl[h] += __shfl_xor_sync(0xffffffffu, pl[h], o);
            pr[h] += __shfl_xor_sync(0xffffffffu, pr[h], o);
        }
    }
    if (lane == 0) {
        g_el4[w] = make_float4(pl[0] * LOG2E, pl[1] * LOG2E, pl[2] * LOG2E, 0.f);
        g_er4[w] = make_float4(pr[0] * LOG2E, pr[1] * LOG2E, pr[2] * LOG2E, 0.f);
    }
}

// ---------------- single-pass online-softmax aggregation, depth-1 pipelined ----------------
__global__ __launch_bounds__(256) void k_agg(const float* __restrict__ b,
                                             const float* __restrict__ Wo,
                                             const float* __restrict__ bo,
                                             float* __restrict__ out) {
    int w = (blockIdx.x * blockDim.x + threadIdx.x) >> 5;
    int lane = threadIdx.x & 31;
    if (w >= NN) return;
    int beg = g_rp[w], end = g_rp[w + 1];
    float4 er = g_er4[w];

    float m0 = -1e30f, m1 = -1e30f, m2 = -1e30f;
    float s0 = 0.f, s1 = 0.f, s2 = 0.f;
    float2 a0 = {0.f, 0.f}, a1 = {0.f, 0.f}, a2 = {0.f, 0.f};

    // rotated software pipeline: edge e+1's loads issue before edge e's math
    float4 elC;
    float2 v0C, v1C, v2C;
    if (beg < end) {
        int s = g_col[beg];
        elC = g_el4[s];
        const float2* f2 = (const float2*)(g_feat + (size_t)s * FH);
        v0C = f2[lane]; v1C = f2[lane + 32]; v2C = f2[lane + 64];
    }
    for (int e = beg; e < end; e++) {
        float4 el = elC;
        float2 v0 = v0C, v1 = v1C, v2 = v2C;
        if (e + 1 < end) {
            int sN = g_col[e + 1];
            elC = g_el4[sN];
            const float2* f2 = (const float2*)(g_feat + (size_t)sN * FH);
            v0C = f2[lane]; v1C = f2[lane + 32]; v2C = f2[lane + 64];
        }
        float x0 = lrelu(el.x + er.x, 0.2f);
        float x1 = lrelu(el.y + er.y, 0.2f);
        float x2 = lrelu(el.z + er.z, 0.2f);
        if (x0 > m0) { float sc = exp2f(m0 - x0); s0 *= sc; a0.x *= sc; a0.y *= sc; m0 = x0; }
        if (x1 > m1) { float sc = exp2f(m1 - x1); s1 *= sc; a1.x *= sc; a1.y *= sc; m1 = x1; }
        if (x2 > m2) { float sc = exp2f(m2 - x2); s2 *= sc; a2.x *= sc; a2.y *= sc; m2 = x2; }
        float w0 = exp2f(x0 - m0), w1 = exp2f(x1 - m1), w2 = exp2f(x2 - m2);
        s0 += w0; s1 += w1; s2 += w2;
        a0.x += w0 * v0.x; a0.y += w0 * v0.y;
        a1.x += w1 * v1.x; a1.y += w1 * v1.y;
        a2.x += w2 * v2.x; a2.y += w2 * v2.y;
    }
    float i0 = s0 > 0.f ? 1.f / s0 : 0.f;
    float i1 = s1 > 0.f ? 1.f / s1 : 0.f;
    float i2 = s2 > 0.f ? 1.f / s2 : 0.f;
    float2 b0 = *(const float2*)(b + 2 * lane);
    float2 b1 = *(const float2*)(b + 64 + 2 * lane);
    float2 b2 = *(const float2*)(b + 128 + 2 * lane);
    float v0x = lrelu(a0.x * i0 + b0.x, 0.01f), v0y = lrelu(a0.y * i0 + b0.y, 0.01f);
    float v1x = lrelu(a1.x * i1 + b1.x, 0.01f), v1y = lrelu(a1.y * i1 + b1.y, 0.01f);
    float v2x = lrelu(a2.x * i2 + b2.x, 0.01f), v2y = lrelu(a2.y * i2 + b2.y, 0.01f);
    float rx = (v0x + v1x + v2x) * (1.f / 3.f);
    float ry = (v0y + v1y + v2y) * (1.f / 3.f);

    if (Wo) {
        #pragma unroll
        for (int c = 0; c < 8; c++) {
            float v = rx * Wo[(2 * lane) * 8 + c] + ry * Wo[(2 * lane + 1) * 8 + c];
            #pragma unroll
            for (int o = 16; o; o >>= 1) v += __shfl_xor_sync(0xffffffffu, v, o);
            if (lane == 0) out[w * 8 + c] = v + bo[c];
        }
    } else {
        __nv_bfloat16 hx = __float2bfloat16(rx);
        __nv_bfloat16 hy = __float2bfloat16(ry);
        __nv_bfloat16 lx = __float2bfloat16(rx - __bfloat162float(hx));
        __nv_bfloat16 ly = __float2bfloat16(ry - __bfloat162float(hy));
        ((__nv_bfloat162*)g_Ahi)[w * 32 + lane] = __nv_bfloat162(hx, hy);
        ((__nv_bfloat162*)g_Alo)[w * 32 + lane] = __nv_bfloat162(lx, ly);
    }
}

// ---------------- launch ----------------
extern "C" void kernel_launch(void* const* d_in, const int* in_sizes, int n_in,
                              void* d_out, int out_size) {
    const float* x   = (const float*)d_in[0];
    const int*   src = (const int*)d_in[1];
    const int*   dst = (const int*)d_in[2];
    const float *W[5], *b[5], *al[5], *ar[5];
    for (int l = 0; l < 5; l++) {
        W[l]  = (const float*)d_in[3 + 4 * l];
        b[l]  = (const float*)d_in[4 + 4 * l];
        al[l] = (const float*)d_in[5 + 4 * l];
        ar[l] = (const float*)d_in[6 + 4 * l];
    }
    const float* Wo = (const float*)d_in[23];
    const float* bo = (const float*)d_in[24];
    float* out = (float*)d_out;

    int nblk = (NN + 1023) / 1024;
    k_zero<<<(NN + 255) / 256, 256>>>();
    k_hist<<<(NE + 255) / 256, 256>>>(dst);
    k_scanA<<<nblk, 1024>>>();
    k_scanB<<<nblk, 1024>>>(nblk);
    k_scatter<<<(NE + 255) / 256, 256>>>(src, dst);

    k_splitW_all<<<(BW_TOT + 255) / 256, 256>>>(W[0], W[1], W[2], W[3], W[4]);
    k_splitA<<<(NN * 128 + 255) / 256, 256>>>(x, NN * 128);

    int wgrid = (NN * 32 + 255) / 256;
    dim3 ggrid((NN + 127) / 128, 2);
    for (int l = 0; l < 5; l++) {
        int boff = (l == 0) ? 0 : 192 * 128 + (l - 1) * 192 * 64;
        if (l == 0) k_gemm_mma<128><<<ggrid, 256>>>(boff);
        else        k_gemm_mma<64><<<ggrid, 256>>>(boff);
        k_attn<<<wgrid, 256>>>(al[l], ar[l]);
        if (l == 4) k_agg<<<wgrid, 256>>>(b[l], Wo, bo, out);
        else        k_agg<<<wgrid, 256>>>(b[l], nullptr, nullptr, nullptr);
    }
}

// round 10
// speedup vs baseline: 1.4136x; 1.0829x over previous
#include <cuda_runtime.h>
#include <cuda_bf16.h>
#include <math.h>
#include <stdint.h>

#define NN 50000
#define NE 800000
#define FH 192          // HEADS*HID
#define HID 64
#define LOG2E 1.4426950408889634f

// ---------------- scratch (static device globals; no allocation) ----------------
__device__ __align__(16) float g_feat[NN * FH];   // 38.4 MB
__device__ __align__(16) __nv_bfloat16 g_Ahi[NN * 128];
__device__ __align__(16) __nv_bfloat16 g_Alo[NN * 128];
#define BW_TOT (192*128 + 4*192*64)
__device__ __align__(16) __nv_bfloat16 g_Bhi5[BW_TOT];
__device__ __align__(16) __nv_bfloat16 g_Blo5[BW_TOT];
__device__ __align__(16) float4 g_el4[NN];
__device__ __align__(16) float4 g_er4[NN];
__device__ int   g_cnt[NN];
__device__ int   g_rp[NN + 1];
__device__ int   g_wp[NN];
__device__ int   g_col[NE];
__device__ int   g_bsum[64];

__device__ __forceinline__ float lrelu(float x, float s) { return x > 0.f ? x : s * x; }

// ---------------- CSR build ----------------
__global__ void k_zero() {
    int i = blockIdx.x * blockDim.x + threadIdx.x;
    if (i < NN) g_cnt[i] = 0;
}
__global__ void k_hist(const int* __restrict__ dst) {
    int e = blockIdx.x * blockDim.x + threadIdx.x;
    if (e < NE) atomicAdd(&g_cnt[dst[e]], 1);
}
__global__ __launch_bounds__(1024) void k_scanA() {
    __shared__ int wsum[32];
    int tid = threadIdx.x, lane = tid & 31, wid = tid >> 5;
    int i = blockIdx.x * 1024 + tid;
    int v = (i < NN) ? g_cnt[i] : 0;
    int x = v;
    #pragma unroll
    for (int o = 1; o < 32; o <<= 1) {
        int t = __shfl_up_sync(0xffffffffu, x, o);
        if (lane >= o) x += t;
    }
    if (lane == 31) wsum[wid] = x;
    __syncthreads();
    if (wid == 0) {
        int y = wsum[lane];
        #pragma unroll
        for (int o = 1; o < 32; o <<= 1) {
            int t = __shfl_up_sync(0xffffffffu, y, o);
            if (lane >= o) y += t;
        }
        wsum[lane] = y;
    }
    __syncthreads();
    int pre = (wid ? wsum[wid - 1] : 0) + x - v;
    if (i < NN) g_rp[i] = pre;
    if (tid == 1023) g_bsum[blockIdx.x] = pre + v;
}
__global__ __launch_bounds__(1024) void k_scanB(int nblk) {
    __shared__ int sb[64];
    int tid = threadIdx.x;
    if (tid < nblk) sb[tid] = g_bsum[tid];
    __syncthreads();
    int off = 0;
    for (int j = 0; j < (int)blockIdx.x; j++) off += sb[j];
    int i = blockIdx.x * 1024 + tid;
    if (i < NN) {
        int v = g_rp[i] + off;
        g_rp[i] = v;
        g_wp[i] = v;
    }
    if (blockIdx.x == gridDim.x - 1 && tid == 0) {
        int tot = 0;
        for (int j = 0; j < nblk; j++) tot += sb[j];
        g_rp[NN] = tot;
    }
}
__global__ void k_scatter(const int* __restrict__ src, const int* __restrict__ dst) {
    int e = blockIdx.x * blockDim.x + threadIdx.x;
    if (e < NE) {
        int p = atomicAdd(&g_wp[dst[e]], 1);
        g_col[p] = src[e];
    }
}

// ---------------- bf16 hi/lo splits ----------------
__global__ void k_splitA(const float* __restrict__ src, int n) {
    int i = blockIdx.x * blockDim.x + threadIdx.x;
    if (i < n) {
        float v = src[i];
        __nv_bfloat16 h = __float2bfloat16(v);
        g_Ahi[i] = h;
        g_Alo[i] = __float2bfloat16(v - __bfloat162float(h));
    }
}
__global__ void k_splitW_all(const float* __restrict__ W0, const float* __restrict__ W1,
                             const float* __restrict__ W2, const float* __restrict__ W3,
                             const float* __restrict__ W4) {
    int i = blockIdx.x * blockDim.x + threadIdx.x;
    if (i >= BW_TOT) return;
    int l, j, K, off;
    if (i < 192 * 128) { l = 0; j = i; K = 128; off = 0; }
    else {
        int r = i - 192 * 128;
        l = 1 + r / (192 * 64);
        j = r % (192 * 64);
        K = 64;
        off = 192 * 128 + (l - 1) * 192 * 64;
    }
    const float* W = (l == 0) ? W0 : (l == 1) ? W1 : (l == 2) ? W2 : (l == 3) ? W3 : W4;
    int k = j / FH, n = j % FH;
    float v = W[j];
    __nv_bfloat16 h = __float2bfloat16(v);
    g_Bhi5[off + n * K + k] = h;
    g_Blo5[off + n * K + k] = __float2bfloat16(v - __bfloat162float(h));
}

// ---------------- mma.sync bf16 split GEMM, 512 threads, block tile 128x192,
// fused attention-logit epilogue (block-local smem reduction, no atomics) ----------------
__device__ __forceinline__ void mma16816(float* d, const uint32_t* a, const uint32_t* b) {
    asm volatile("mma.sync.aligned.m16n8k16.row.col.f32.bf16.bf16.f32 "
        "{%0,%1,%2,%3}, {%4,%5,%6,%7}, {%8,%9}, {%0,%1,%2,%3};"
        : "+f"(d[0]), "+f"(d[1]), "+f"(d[2]), "+f"(d[3])
        : "r"(a[0]), "r"(a[1]), "r"(a[2]), "r"(a[3]), "r"(b[0]), "r"(b[1]));
}
#define ASTR 24

template <int K>
__global__ __launch_bounds__(512, 1) void k_gemm_mma(int boff, const float* __restrict__ al,
                                                     const float* __restrict__ ar) {
    __shared__ __nv_bfloat16 As[2][128 * ASTR];
    __shared__ __nv_bfloat16 Bs[2][192 * ASTR];
    __shared__ float s_el[4][128][3];
    __shared__ float s_er[4][128][3];
    int tid = threadIdx.x, lane = tid & 31, w = tid >> 5;
    int mw = w & 3, nw = w >> 2;      // 4x4 warp grid
    int m0 = blockIdx.x * 128;
    int g = lane >> 2, t = lane & 3;

    float d[2][6][4];
    #pragma unroll
    for (int i = 0; i < 2; i++)
        #pragma unroll
        for (int j = 0; j < 6; j++)
            #pragma unroll
            for (int q = 0; q < 4; q++) d[i][j][q] = 0.f;

    for (int k0 = 0; k0 < K; k0 += 16) {
        // A: 128 rows x 2 halves x 2 16B-chunks = 512 uint4 -> 1/thread
        {
            int half = tid >> 8, j = tid & 255;
            int r = j >> 1, p = j & 1;
            const __nv_bfloat16* src = half ? g_Alo : g_Ahi;
            uint4 v = make_uint4(0u, 0u, 0u, 0u);
            if (m0 + r < NN)
                v = *(const uint4*)(src + (size_t)(m0 + r) * K + k0 + p * 8);
            *(uint4*)(&As[half][r * ASTR + p * 8]) = v;
        }
        // B: 192 rows x 2 halves x 2 chunks = 768 uint4
        #pragma unroll
        for (int ii = 0; ii < 2; ii++) {
            int idx = tid + ii * 512;
            if (idx < 768) {
                int half = idx / 384, j = idx % 384;
                int r = j >> 1, p = j & 1;
                const __nv_bfloat16* src = (half ? g_Blo5 : g_Bhi5) + boff;
                uint4 v = *(const uint4*)(src + r * K + k0 + p * 8);
                *(uint4*)(&Bs[half][r * ASTR + p * 8]) = v;
            }
        }
        __syncthreads();

        uint32_t afr[2][2][4];
        #pragma unroll
        for (int half = 0; half < 2; half++)
            #pragma unroll
            for (int mt = 0; mt < 2; mt++) {
                const __nv_bfloat16* base = &As[half][(mw * 32 + mt * 16) * ASTR];
                afr[half][mt][0] = *(const uint32_t*)(base + g * ASTR + 2 * t);
                afr[half][mt][1] = *(const uint32_t*)(base + (g + 8) * ASTR + 2 * t);
                afr[half][mt][2] = *(const uint32_t*)(base + g * ASTR + 2 * t + 8);
                afr[half][mt][3] = *(const uint32_t*)(base + (g + 8) * ASTR + 2 * t + 8);
            }
        uint32_t bfr[2][6][2];
        #pragma unroll
        for (int half = 0; half < 2; half++)
            #pragma unroll
            for (int nt = 0; nt < 6; nt++) {
                const __nv_bfloat16* base = &Bs[half][(nw * 48 + nt * 8) * ASTR];
                bfr[half][nt][0] = *(const uint32_t*)(base + g * ASTR + 2 * t);
                bfr[half][nt][1] = *(const uint32_t*)(base + g * ASTR + 2 * t + 8);
            }
        #pragma unroll
        for (int mt = 0; mt < 2; mt++)
            #pragma unroll
            for (int nt = 0; nt < 6; nt++) {
                mma16816(d[mt][nt], afr[0][mt], bfr[0][nt]);
                mma16816(d[mt][nt], afr[0][mt], bfr[1][nt]);
                mma16816(d[mt][nt], afr[1][mt], bfr[0][nt]);
            }
        __syncthreads();
    }

    // feat store
    #pragma unroll
    for (int mt = 0; mt < 2; mt++) {
        int r0 = m0 + mw * 32 + mt * 16 + g;
        #pragma unroll
        for (int nt = 0; nt < 6; nt++) {
            int c = nw * 48 + nt * 8 + 2 * t;
            if (r0 < NN)
                *(float2*)&g_feat[(size_t)r0 * FH + c] = make_float2(d[mt][nt][0], d[mt][nt][1]);
            if (r0 + 8 < NN)
                *(float2*)&g_feat[(size_t)(r0 + 8) * FH + c] = make_float2(d[mt][nt][2], d[mt][nt][3]);
        }
    }

    // fused attention logits: this warp's 48-col slice spans heads hA..hB
    int n0q = nw * 48;
    int hA = n0q >> 6, hB = (n0q + 47) >> 6;
    float pelA[2][2] = {{0.f,0.f},{0.f,0.f}}, pelB[2][2] = {{0.f,0.f},{0.f,0.f}};
    float perA[2][2] = {{0.f,0.f},{0.f,0.f}}, perB[2][2] = {{0.f,0.f},{0.f,0.f}};
    #pragma unroll
    for (int nt = 0; nt < 6; nt++) {
        int c = n0q + nt * 8 + 2 * t;
        float a0 = al[c] * LOG2E, a1 = al[c + 1] * LOG2E;
        float r0v = ar[c] * LOG2E, r1v = ar[c + 1] * LOG2E;
        bool isA = ((n0q + nt * 8) >> 6) == hA;
        #pragma unroll
        for (int mt = 0; mt < 2; mt++) {
            float el_g  = d[mt][nt][0] * a0 + d[mt][nt][1] * a1;
            float el_g8 = d[mt][nt][2] * a0 + d[mt][nt][3] * a1;
            float er_g  = d[mt][nt][0] * r0v + d[mt][nt][1] * r1v;
            float er_g8 = d[mt][nt][2] * r0v + d[mt][nt][3] * r1v;
            if (isA) { pelA[mt][0] += el_g; pelA[mt][1] += el_g8;
                       perA[mt][0] += er_g; perA[mt][1] += er_g8; }
            else     { pelB[mt][0] += el_g; pelB[mt][1] += el_g8;
                       perB[mt][0] += er_g; perB[mt][1] += er_g8; }
        }
    }
    #pragma unroll
    for (int mt = 0; mt < 2; mt++)
        #pragma unroll
        for (int gg = 0; gg < 2; gg++)
            #pragma unroll
            for (int o = 1; o <= 2; o <<= 1) {
                pelA[mt][gg] += __shfl_xor_sync(0xffffffffu, pelA[mt][gg], o);
                pelB[mt][gg] += __shfl_xor_sync(0xffffffffu, pelB[mt][gg], o);
                perA[mt][gg] += __shfl_xor_sync(0xffffffffu, perA[mt][gg], o);
                perB[mt][gg] += __shfl_xor_sync(0xffffffffu, perB[mt][gg], o);
            }
    if (t == 0) {
        #pragma unroll
        for (int mt = 0; mt < 2; mt++)
            #pragma unroll
            for (int gg = 0; gg < 2; gg++) {
                int rl = mw * 32 + mt * 16 + g + gg * 8;  // 0..127
                #pragma unroll
                for (int h = 0; h < 3; h++) {
                    float ve = (h == hA) ? pelA[mt][gg] : (h == hB) ? pelB[mt][gg] : 0.f;
                    float vr = (h == hA) ? perA[mt][gg] : (h == hB) ? perB[mt][gg] : 0.f;
                    s_el[nw][rl][h] = ve;
                    s_er[nw][rl][h] = vr;
                }
            }
    }
    __syncthreads();
    // final reduction over nw: 128 rows x 3 heads = 384 entries
    if (tid < 384) {
        int row = tid / 3, h = tid % 3;
        float se = s_el[0][row][h] + s_el[1][row][h] + s_el[2][row][h] + s_el[3][row][h];
        float sr = s_er[0][row][h] + s_er[1][row][h] + s_er[2][row][h] + s_er[3][row][h];
        int r = m0 + row;
        if (r < NN) {
            ((float*)&g_el4[r])[h] = se;
            ((float*)&g_er4[r])[h] = sr;
        }
    }
}

// ---------------- single-pass online-softmax aggregation (round-7 form) ----------------
__global__ __launch_bounds__(256) void k_agg(const float* __restrict__ b,
                                             const float* __restrict__ Wo,
                                             const float* __restrict__ bo,
                                             float* __restrict__ out) {
    int w = (blockIdx.x * blockDim.x + threadIdx.x) >> 5;
    int lane = threadIdx.x & 31;
    if (w >= NN) return;
    int beg = g_rp[w], end = g_rp[w + 1];
    float4 er = g_er4[w];

    float m0 = -1e30f, m1 = -1e30f, m2 = -1e30f;
    float s0 = 0.f, s1 = 0.f, s2 = 0.f;
    float2 a0 = {0.f, 0.f}, a1 = {0.f, 0.f}, a2 = {0.f, 0.f};

    for (int e = beg; e < end; e++) {
        int s = g_col[e];
        float4 el = g_el4[s];
        float x0 = lrelu(el.x + er.x, 0.2f);
        float x1 = lrelu(el.y + er.y, 0.2f);
        float x2 = lrelu(el.z + er.z, 0.2f);
        if (x0 > m0) { float sc = exp2f(m0 - x0); s0 *= sc; a0.x *= sc; a0.y *= sc; m0 = x0; }
        if (x1 > m1) { float sc = exp2f(m1 - x1); s1 *= sc; a1.x *= sc; a1.y *= sc; m1 = x1; }
        if (x2 > m2) { float sc = exp2f(m2 - x2); s2 *= sc; a2.x *= sc; a2.y *= sc; m2 = x2; }
        float w0 = exp2f(x0 - m0), w1 = exp2f(x1 - m1), w2 = exp2f(x2 - m2);
        s0 += w0; s1 += w1; s2 += w2;
        const float2* f2 = (const float2*)(g_feat + (size_t)s * FH);
        float2 v0 = f2[lane], v1 = f2[lane + 32], v2 = f2[lane + 64];
        a0.x += w0 * v0.x; a0.y += w0 * v0.y;
        a1.x += w1 * v1.x; a1.y += w1 * v1.y;
        a2.x += w2 * v2.x; a2.y += w2 * v2.y;
    }
    float i0 = s0 > 0.f ? 1.f / s0 : 0.f;
    float i1 = s1 > 0.f ? 1.f / s1 : 0.f;
    float i2 = s2 > 0.f ? 1.f / s2 : 0.f;
    float2 b0 = *(const float2*)(b + 2 * lane);
    float2 b1 = *(const float2*)(b + 64 + 2 * lane);
    float2 b2 = *(const float2*)(b + 128 + 2 * lane);
    float v0x = lrelu(a0.x * i0 + b0.x, 0.01f), v0y = lrelu(a0.y * i0 + b0.y, 0.01f);
    float v1x = lrelu(a1.x * i1 + b1.x, 0.01f), v1y = lrelu(a1.y * i1 + b1.y, 0.01f);
    float v2x = lrelu(a2.x * i2 + b2.x, 0.01f), v2y = lrelu(a2.y * i2 + b2.y, 0.01f);
    float rx = (v0x + v1x + v2x) * (1.f / 3.f);
    float ry = (v0y + v1y + v2y) * (1.f / 3.f);

    if (Wo) {
        #pragma unroll
        for (int c = 0; c < 8; c++) {
            float v = rx * Wo[(2 * lane) * 8 + c] + ry * Wo[(2 * lane + 1) * 8 + c];
            #pragma unroll
            for (int o = 16; o; o >>= 1) v += __shfl_xor_sync(0xffffffffu, v, o);
            if (lane == 0) out[w * 8 + c] = v + bo[c];
        }
    } else {
        __nv_bfloat16 hx = __float2bfloat16(rx);
        __nv_bfloat16 hy = __float2bfloat16(ry);
        __nv_bfloat16 lx = __float2bfloat16(rx - __bfloat162float(hx));
        __nv_bfloat16 ly = __float2bfloat16(ry - __bfloat162float(hy));
        ((__nv_bfloat162*)g_Ahi)[w * 32 + lane] = __nv_bfloat162(hx, hy);
        ((__nv_bfloat162*)g_Alo)[w * 32 + lane] = __nv_bfloat162(lx, ly);
    }
}

// ---------------- launch ----------------
extern "C" void kernel_launch(void* const* d_in, const int* in_sizes, int n_in,
                              void* d_out, int out_size) {
    const float* x   = (const float*)d_in[0];
    const int*   src = (const int*)d_in[1];
    const int*   dst = (const int*)d_in[2];
    const float *W[5], *b[5], *al[5], *ar[5];
    for (int l = 0; l < 5; l++) {
        W[l]  = (const float*)d_in[3 + 4 * l];
        b[l]  = (const float*)d_in[4 + 4 * l];
        al[l] = (const float*)d_in[5 + 4 * l];
        ar[l] = (const float*)d_in[6 + 4 * l];
    }
    const float* Wo = (const float*)d_in[23];
    const float* bo = (const float*)d_in[24];
    float* out = (float*)d_out;

    int nblk = (NN + 1023) / 1024;
    k_zero<<<(NN + 255) / 256, 256>>>();
    k_hist<<<(NE + 255) / 256, 256>>>(dst);
    k_scanA<<<nblk, 1024>>>();
    k_scanB<<<nblk, 1024>>>(nblk);
    k_scatter<<<(NE + 255) / 256, 256>>>(src, dst);

    k_splitW_all<<<(BW_TOT + 255) / 256, 256>>>(W[0], W[1], W[2], W[3], W[4]);
    k_splitA<<<(NN * 128 + 255) / 256, 256>>>(x, NN * 128);

    int wgrid = (NN * 32 + 255) / 256;
    int ggrid = (NN + 127) / 128;
    for (int l = 0; l < 5; l++) {
        int boff = (l == 0) ? 0 : 192 * 128 + (l - 1) * 192 * 64;
        if (l == 0) k_gemm_mma<128><<<ggrid, 512>>>(boff, al[l], ar[l]);
        else        k_gemm_mma<64><<<ggrid, 512>>>(boff, al[l], ar[l]);
        if (l == 4) k_agg<<<wgrid, 256>>>(b[l], Wo, bo, out);
        else        k_agg<<<wgrid, 256>>>(b[l], nullptr, nullptr, nullptr);
    }
}

// round 12
// speedup vs baseline: 1.5024x; 1.0628x over previous
#include <cuda_runtime.h>
#include <cuda_bf16.h>
#include <math.h>
#include <stdint.h>

#define NN 50000
#define NE 800000
#define FH 192          // HEADS*HID
#define HID 64
#define LOG2E 1.4426950408889634f

// ---------------- scratch (static device globals; no allocation) ----------------
__device__ __align__(16) float g_feat[NN * FH];   // 38.4 MB
__device__ __align__(16) __nv_bfloat16 g_Ahi[NN * 128];
__device__ __align__(16) __nv_bfloat16 g_Alo[NN * 128];
#define BW_TOT (192*128 + 4*192*64)
__device__ __align__(16) __nv_bfloat16 g_Bhi5[BW_TOT];
__device__ __align__(16) __nv_bfloat16 g_Blo5[BW_TOT];
__device__ __align__(16) float4 g_el4[NN];
__device__ __align__(16) float4 g_er4[NN];
__device__ int   g_cnt[NN];
__device__ int   g_rp[NN + 1];
__device__ int   g_wp[NN];
__device__ int   g_col[NE];
__device__ int   g_bsum[64];

__device__ __forceinline__ float lrelu(float x, float s) { return x > 0.f ? x : s * x; }

// ---------------- cp.async helpers ----------------
__device__ __forceinline__ void cpasync16(uint32_t saddr, const void* gaddr, uint32_t srcbytes) {
    asm volatile("cp.async.ca.shared.global [%0], [%1], 16, %2;"
                 :: "r"(saddr), "l"(gaddr), "r"(srcbytes));
}
__device__ __forceinline__ void cp_commit() {
    asm volatile("cp.async.commit_group;");
}
template <int N>
__device__ __forceinline__ void cp_wait() {
    asm volatile("cp.async.wait_group %0;" :: "n"(N));
}

// ---------------- CSR build ----------------
__global__ void k_hist(const int* __restrict__ dst) {
    int e = blockIdx.x * blockDim.x + threadIdx.x;
    if (e < NE) atomicAdd(&g_cnt[dst[e]], 1);
}
__global__ __launch_bounds__(1024) void k_scanA() {
    __shared__ int wsum[32];
    int tid = threadIdx.x, lane = tid & 31, wid = tid >> 5;
    int i = blockIdx.x * 1024 + tid;
    int v = (i < NN) ? g_cnt[i] : 0;
    int x = v;
    #pragma unroll
    for (int o = 1; o < 32; o <<= 1) {
        int t = __shfl_up_sync(0xffffffffu, x, o);
        if (lane >= o) x += t;
    }
    if (lane == 31) wsum[wid] = x;
    __syncthreads();
    if (wid == 0) {
        int y = wsum[lane];
        #pragma unroll
        for (int o = 1; o < 32; o <<= 1) {
            int t = __shfl_up_sync(0xffffffffu, y, o);
            if (lane >= o) y += t;
        }
        wsum[lane] = y;
    }
    __syncthreads();
    int pre = (wid ? wsum[wid - 1] : 0) + x - v;
    if (i < NN) g_rp[i] = pre;
    if (tid == 1023) g_bsum[blockIdx.x] = pre + v;
}
__global__ __launch_bounds__(1024) void k_scanB(int nblk) {
    __shared__ int sb[64];
    int tid = threadIdx.x;
    if (tid < nblk) sb[tid] = g_bsum[tid];
    __syncthreads();
    int off = 0;
    for (int j = 0; j < (int)blockIdx.x; j++) off += sb[j];
    int i = blockIdx.x * 1024 + tid;
    if (i < NN) {
        int v = g_rp[i] + off;
        g_rp[i] = v;
        g_wp[i] = v;
    }
    if (blockIdx.x == gridDim.x - 1 && tid == 0) {
        int tot = 0;
        for (int j = 0; j < nblk; j++) tot += sb[j];
        g_rp[NN] = tot;
    }
}
__global__ void k_scatter(const int* __restrict__ src, const int* __restrict__ dst) {
    int e = blockIdx.x * blockDim.x + threadIdx.x;
    if (e < NE) {
        int p = atomicAdd(&g_wp[dst[e]], 1);
        g_col[p] = src[e];
    }
}

// ---------------- prep: zero cnt + split all weights + split input ----------------
__global__ void k_prep(const float* __restrict__ x,
                       const float* __restrict__ W0, const float* __restrict__ W1,
                       const float* __restrict__ W2, const float* __restrict__ W3,
                       const float* __restrict__ W4) {
    int i = blockIdx.x * blockDim.x + threadIdx.x;
    if (i < NN) g_cnt[i] = 0;
    if (i < BW_TOT) {
        int l, j, K, off;
        if (i < 192 * 128) { l = 0; j = i; K = 128; off = 0; }
        else {
            int r = i - 192 * 128;
            l = 1 + r / (192 * 64);
            j = r % (192 * 64);
            K = 64;
            off = 192 * 128 + (l - 1) * 192 * 64;
        }
        const float* W = (l == 0) ? W0 : (l == 1) ? W1 : (l == 2) ? W2 : (l == 3) ? W3 : W4;
        int k = j / FH, n = j % FH;
        float v = W[j];
        __nv_bfloat16 h = __float2bfloat16(v);
        g_Bhi5[off + n * K + k] = h;
        g_Blo5[off + n * K + k] = __float2bfloat16(v - __bfloat162float(h));
    }
    if (i < NN * 128) {
        float v = x[i];
        __nv_bfloat16 h = __float2bfloat16(v);
        g_Ahi[i] = h;
        g_Alo[i] = __float2bfloat16(v - __bfloat162float(h));
    }
}

// ---------------- mma.sync bf16 split GEMM, 512 threads, 128x192 tile,
// two-stage cp.async double buffer + fused attention-logit epilogue ----------------
__device__ __forceinline__ void mma16816(float* d, const uint32_t* a, const uint32_t* b) {
    asm volatile("mma.sync.aligned.m16n8k16.row.col.f32.bf16.bf16.f32 "
        "{%0,%1,%2,%3}, {%4,%5,%6,%7}, {%8,%9}, {%0,%1,%2,%3};"
        : "+f"(d[0]), "+f"(d[1]), "+f"(d[2]), "+f"(d[3])
        : "r"(a[0]), "r"(a[1]), "r"(a[2]), "r"(a[3]), "r"(b[0]), "r"(b[1]));
}
#define ASTR 24
// dynamic smem layout (bf16 elements):
//  sA: 2buf x 2half x 3072   (128*ASTR)      = 12288 elems
//  sB: 2buf x 2half x 4608   (192*ASTR)      = 18432 elems
//  s_el/s_er: 4*128*3 floats each
#define SM_A_ELE 3072
#define SM_B_ELE 4608
#define SM_B_OFF 12288
#define SM_EL_OFF ((12288 + 18432) * 2)   // byte offset of s_el
#define SM_TOTAL (SM_EL_OFF + 2 * 1536 * 4)

template <int K>
__global__ __launch_bounds__(512, 1) void k_gemm_mma(int boff, const float* __restrict__ al,
                                                     const float* __restrict__ ar) {
    extern __shared__ __nv_bfloat16 smem[];
    __nv_bfloat16* sA = smem;
    __nv_bfloat16* sB = smem + SM_B_OFF;
    float* s_el = (float*)((char*)smem + SM_EL_OFF);
    float* s_er = s_el + 1536;
    const int NT = K / 16;

    int tid = threadIdx.x, lane = tid & 31, w = tid >> 5;
    int mw = w & 3, nw = w >> 2;
    int m0 = blockIdx.x * 128;
    int g = lane >> 2, t = lane & 3;

    // --- per-thread copy descriptors ---
    // A: 512 chunks = 128 rows x 2 halves x 2 16B-chunks, 1 per thread
    int halfA = tid >> 8, jA = tid & 255, rA = jA >> 1, pA = jA & 1;
    const __nv_bfloat16* gA = (halfA ? g_Alo : g_Ahi) + (size_t)(m0 + rA) * K + pA * 8;
    uint32_t okA = (m0 + rA < NN) ? 16u : 0u;
    uint32_t sAb = (uint32_t)__cvta_generic_to_shared(sA);
    uint32_t dstA0 = sAb + (uint32_t)(halfA * SM_A_ELE + rA * ASTR + pA * 8) * 2;
    // B chunk 0: idx = tid (<512 -> half = tid/384)
    int half0 = tid / 384, j0 = tid % 384, r0 = j0 >> 1, p0 = j0 & 1;
    const __nv_bfloat16* gB0 = (half0 ? g_Blo5 : g_Bhi5) + boff + r0 * K + p0 * 8;
    uint32_t sBb = (uint32_t)__cvta_generic_to_shared(sB);
    uint32_t dstB00 = sBb + (uint32_t)(half0 * SM_B_ELE + r0 * ASTR + p0 * 8) * 2;
    // B chunk 1: idx = tid+512 in [512,768) -> half=1, j = tid+128 (only tid<256)
    int j1 = tid + 128, r1 = j1 >> 1, p1 = j1 & 1;
    const __nv_bfloat16* gB1 = g_Blo5 + boff + r1 * K + p1 * 8;
    uint32_t dstB10 = sBb + (uint32_t)(SM_B_ELE + r1 * ASTR + p1 * 8) * 2;

    float d[2][6][4];
    #pragma unroll
    for (int i = 0; i < 2; i++)
        #pragma unroll
        for (int j = 0; j < 6; j++)
            #pragma unroll
            for (int q = 0; q < 4; q++) d[i][j][q] = 0.f;

    // prologue: stage tile 0 into buf 0
    cpasync16(dstA0, gA, okA);
    cpasync16(dstB00, gB0, 16u);
    if (tid < 256) cpasync16(dstB10, gB1, 16u);
    cp_commit();

    #pragma unroll
    for (int kt = 0; kt < NT; kt++) {
        int buf = kt & 1;
        if (kt + 1 < NT) {
            int nbuf = (kt + 1) & 1;
            int k0 = (kt + 1) * 16;
            cpasync16(dstA0 + nbuf * (2 * SM_A_ELE * 2), gA + k0, okA);
            cpasync16(dstB00 + nbuf * (2 * SM_B_ELE * 2), gB0 + k0, 16u);
            if (tid < 256) cpasync16(dstB10 + nbuf * (2 * SM_B_ELE * 2), gB1 + k0, 16u);
            cp_commit();
            cp_wait<1>();
        } else {
            cp_wait<0>();
        }
        __syncthreads();

        const __nv_bfloat16* Abuf = sA + buf * 2 * SM_A_ELE;
        const __nv_bfloat16* Bbuf = sB + buf * 2 * SM_B_ELE;
        uint32_t afr[2][2][4];
        #pragma unroll
        for (int half = 0; half < 2; half++)
            #pragma unroll
            for (int mt = 0; mt < 2; mt++) {
                const __nv_bfloat16* base = Abuf + half * SM_A_ELE + (mw * 32 + mt * 16) * ASTR;
                afr[half][mt][0] = *(const uint32_t*)(base + g * ASTR + 2 * t);
                afr[half][mt][1] = *(const uint32_t*)(base + (g + 8) * ASTR + 2 * t);
                afr[half][mt][2] = *(const uint32_t*)(base + g * ASTR + 2 * t + 8);
                afr[half][mt][3] = *(const uint32_t*)(base + (g + 8) * ASTR + 2 * t + 8);
            }
        uint32_t bfr[2][6][2];
        #pragma unroll
        for (int half = 0; half < 2; half++)
            #pragma unroll
            for (int nt = 0; nt < 6; nt++) {
                const __nv_bfloat16* base = Bbuf + half * SM_B_ELE + (nw * 48 + nt * 8) * ASTR;
                bfr[half][nt][0] = *(const uint32_t*)(base + g * ASTR + 2 * t);
                bfr[half][nt][1] = *(const uint32_t*)(base + g * ASTR + 2 * t + 8);
            }
        #pragma unroll
        for (int mt = 0; mt < 2; mt++)
            #pragma unroll
            for (int nt = 0; nt < 6; nt++) {
                mma16816(d[mt][nt], afr[0][mt], bfr[0][nt]);
                mma16816(d[mt][nt], afr[0][mt], bfr[1][nt]);
                mma16816(d[mt][nt], afr[1][mt], bfr[0][nt]);
            }
        __syncthreads();
    }

    // feat store
    #pragma unroll
    for (int mt = 0; mt < 2; mt++) {
        int r0s = m0 + mw * 32 + mt * 16 + g;
        #pragma unroll
        for (int nt = 0; nt < 6; nt++) {
            int c = nw * 48 + nt * 8 + 2 * t;
            if (r0s < NN)
                *(float2*)&g_feat[(size_t)r0s * FH + c] = make_float2(d[mt][nt][0], d[mt][nt][1]);
            if (r0s + 8 < NN)
                *(float2*)&g_feat[(size_t)(r0s + 8) * FH + c] = make_float2(d[mt][nt][2], d[mt][nt][3]);
        }
    }

    // fused attention logits
    int n0q = nw * 48;
    int hA = n0q >> 6, hB = (n0q + 47) >> 6;
    float pelA[2][2] = {{0.f,0.f},{0.f,0.f}}, pelB[2][2] = {{0.f,0.f},{0.f,0.f}};
    float perA[2][2] = {{0.f,0.f},{0.f,0.f}}, perB[2][2] = {{0.f,0.f},{0.f,0.f}};
    #pragma unroll
    for (int nt = 0; nt < 6; nt++) {
        int c = n0q + nt * 8 + 2 * t;
        float a0 = al[c] * LOG2E, a1 = al[c + 1] * LOG2E;
        float r0v = ar[c] * LOG2E, r1v = ar[c + 1] * LOG2E;
        bool isA = ((n0q + nt * 8) >> 6) == hA;
        #pragma unroll
        for (int mt = 0; mt < 2; mt++) {
            float el_g  = d[mt][nt][0] * a0 + d[mt][nt][1] * a1;
            float el_g8 = d[mt][nt][2] * a0 + d[mt][nt][3] * a1;
            float er_g  = d[mt][nt][0] * r0v + d[mt][nt][1] * r1v;
            float er_g8 = d[mt][nt][2] * r0v + d[mt][nt][3] * r1v;
            if (isA) { pelA[mt][0] += el_g; pelA[mt][1] += el_g8;
                       perA[mt][0] += er_g; perA[mt][1] += er_g8; }
            else     { pelB[mt][0] += el_g; pelB[mt][1] += el_g8;
                       perB[mt][0] += er_g; perB[mt][1] += er_g8; }
        }
    }
    #pragma unroll
    for (int mt = 0; mt < 2; mt++)
        #pragma unroll
        for (int gg = 0; gg < 2; gg++)
            #pragma unroll
            for (int o = 1; o <= 2; o <<= 1) {
                pelA[mt][gg] += __shfl_xor_sync(0xffffffffu, pelA[mt][gg], o);
                pelB[mt][gg] += __shfl_xor_sync(0xffffffffu, pelB[mt][gg], o);
                perA[mt][gg] += __shfl_xor_sync(0xffffffffu, perA[mt][gg], o);
                perB[mt][gg] += __shfl_xor_sync(0xffffffffu, perB[mt][gg], o);
            }
    if (t == 0) {
        #pragma unroll
        for (int mt = 0; mt < 2; mt++)
            #pragma unroll
            for (int gg = 0; gg < 2; gg++) {
                int rl = mw * 32 + mt * 16 + g + gg * 8;
                #pragma unroll
                for (int h = 0; h < 3; h++) {
                    float ve = (h == hA) ? pelA[mt][gg] : (h == hB) ? pelB[mt][gg] : 0.f;
                    float vr = (h == hA) ? perA[mt][gg] : (h == hB) ? perB[mt][gg] : 0.f;
                    s_el[(nw * 128 + rl) * 3 + h] = ve;
                    s_er[(nw * 128 + rl) * 3 + h] = vr;
                }
            }
    }
    __syncthreads();
    if (tid < 384) {
        int row = tid / 3, h = tid % 3;
        float se = s_el[row * 3 + h] + s_el[(128 + row) * 3 + h]
                 + s_el[(256 + row) * 3 + h] + s_el[(384 + row) * 3 + h];
        float sr = s_er[row * 3 + h] + s_er[(128 + row) * 3 + h]
                 + s_er[(256 + row) * 3 + h] + s_er[(384 + row) * 3 + h];
        int r = m0 + row;
        if (r < NN) {
            ((float*)&g_el4[r])[h] = se;
            ((float*)&g_er4[r])[h] = sr;
        }
    }
}

// ---------------- single-pass online-softmax aggregation ----------------
__global__ __launch_bounds__(256) void k_agg(const float* __restrict__ b,
                                             const float* __restrict__ Wo,
                                             const float* __restrict__ bo,
                                             float* __restrict__ out) {
    int w = (blockIdx.x * blockDim.x + threadIdx.x) >> 5;
    int lane = threadIdx.x & 31;
    if (w >= NN) return;
    int beg = g_rp[w], end = g_rp[w + 1];
    float4 er = g_er4[w];

    float m0 = -1e30f, m1 = -1e30f, m2 = -1e30f;
    float s0 = 0.f, s1 = 0.f, s2 = 0.f;
    float2 a0 = {0.f, 0.f}, a1 = {0.f, 0.f}, a2 = {0.f, 0.f};

    for (int e = beg; e < end; e++) {
        int s = g_col[e];
        float4 el = g_el4[s];
        float x0 = lrelu(el.x + er.x, 0.2f);
        float x1 = lrelu(el.y + er.y, 0.2f);
        float x2 = lrelu(el.z + er.z, 0.2f);
        if (x0 > m0) { float sc = exp2f(m0 - x0); s0 *= sc; a0.x *= sc; a0.y *= sc; m0 = x0; }
        if (x1 > m1) { float sc = exp2f(m1 - x1); s1 *= sc; a1.x *= sc; a1.y *= sc; m1 = x1; }
        if (x2 > m2) { float sc = exp2f(m2 - x2); s2 *= sc; a2.x *= sc; a2.y *= sc; m2 = x2; }
        float w0 = exp2f(x0 - m0), w1 = exp2f(x1 - m1), w2 = exp2f(x2 - m2);
        s0 += w0; s1 += w1; s2 += w2;
        const float2* f2 = (const float2*)(g_feat + (size_t)s * FH);
        float2 v0 = f2[lane], v1 = f2[lane + 32], v2 = f2[lane + 64];
        a0.x += w0 * v0.x; a0.y += w0 * v0.y;
        a1.x += w1 * v1.x; a1.y += w1 * v1.y;
        a2.x += w2 * v2.x; a2.y += w2 * v2.y;
    }
    float i0 = s0 > 0.f ? 1.f / s0 : 0.f;
    float i1 = s1 > 0.f ? 1.f / s1 : 0.f;
    float i2 = s2 > 0.f ? 1.f / s2 : 0.f;
    float2 b0 = *(const float2*)(b + 2 * lane);
    float2 b1 = *(const float2*)(b + 64 + 2 * lane);
    float2 b2 = *(const float2*)(b + 128 + 2 * lane);
    float v0x = lrelu(a0.x * i0 + b0.x, 0.01f), v0y = lrelu(a0.y * i0 + b0.y, 0.01f);
    float v1x = lrelu(a1.x * i1 + b1.x, 0.01f), v1y = lrelu(a1.y * i1 + b1.y, 0.01f);
    float v2x = lrelu(a2.x * i2 + b2.x, 0.01f), v2y = lrelu(a2.y * i2 + b2.y, 0.01f);
    float rx = (v0x + v1x + v2x) * (1.f / 3.f);
    float ry = (v0y + v1y + v2y) * (1.f / 3.f);

    if (Wo) {
        #pragma unroll
        for (int c = 0; c < 8; c++) {
            float v = rx * Wo[(2 * lane) * 8 + c] + ry * Wo[(2 * lane + 1) * 8 + c];
            #pragma unroll
            for (int o = 16; o; o >>= 1) v += __shfl_xor_sync(0xffffffffu, v, o);
            if (lane == 0) out[w * 8 + c] = v + bo[c];
        }
    } else {
        __nv_bfloat16 hx = __float2bfloat16(rx);
        __nv_bfloat16 hy = __float2bfloat16(ry);
        __nv_bfloat16 lx = __float2bfloat16(rx - __bfloat162float(hx));
        __nv_bfloat16 ly = __float2bfloat16(ry - __bfloat162float(hy));
        ((__nv_bfloat162*)g_Ahi)[w * 32 + lane] = __nv_bfloat162(hx, hy);
        ((__nv_bfloat162*)g_Alo)[w * 32 + lane] = __nv_bfloat162(lx, ly);
    }
}

// ---------------- launch ----------------
extern "C" void kernel_launch(void* const* d_in, const int* in_sizes, int n_in,
                              void* d_out, int out_size) {
    const float* x   = (const float*)d_in[0];
    const int*   src = (const int*)d_in[1];
    const int*   dst = (const int*)d_in[2];
    const float *W[5], *b[5], *al[5], *ar[5];
    for (int l = 0; l < 5; l++) {
        W[l]  = (const float*)d_in[3 + 4 * l];
        b[l]  = (const float*)d_in[4 + 4 * l];
        al[l] = (const float*)d_in[5 + 4 * l];
        ar[l] = (const float*)d_in[6 + 4 * l];
    }
    const float* Wo = (const float*)d_in[23];
    const float* bo = (const float*)d_in[24];
    float* out = (float*)d_out;

    cudaFuncSetAttribute(k_gemm_mma<128>, cudaFuncAttributeMaxDynamicSharedMemorySize, SM_TOTAL);
    cudaFuncSetAttribute(k_gemm_mma<64>,  cudaFuncAttributeMaxDynamicSharedMemorySize, SM_TOTAL);

    // prep (zero cnt + all splits) runs first; CSR chain follows
    k_prep<<<(NN * 128 + 255) / 256, 256>>>(x, W[0], W[1], W[2], W[3], W[4]);

    int nblk = (NN + 1023) / 1024;
    k_hist<<<(NE + 255) / 256, 256>>>(dst);
    k_scanA<<<nblk, 1024>>>();
    k_scanB<<<nblk, 1024>>>(nblk);
    k_scatter<<<(NE + 255) / 256, 256>>>(src, dst);

    int wgrid = (NN * 32 + 255) / 256;
    int ggrid = (NN + 127) / 128;
    for (int l = 0; l < 5; l++) {
        int boff = (l == 0) ? 0 : 192 * 128 + (l - 1) * 192 * 64;
        if (l == 0) k_gemm_mma<128><<<ggrid, 512, SM_TOTAL>>>(boff, al[l], ar[l]);
        else        k_gemm_mma<64><<<ggrid, 512, SM_TOTAL>>>(boff, al[l], ar[l]);
        if (l == 4) k_agg<<<wgrid, 256>>>(b[l], Wo, bo, out);
        else        k_agg<<<wgrid, 256>>>(b[l], nullptr, nullptr, nullptr);
    }
}

// round 14
// speedup vs baseline: 1.5349x; 1.0216x over previous
#include <cuda_runtime.h>
#include <cuda_bf16.h>
#include <math.h>
#include <stdint.h>

#define NN 50000
#define NE 800000
#define FH 192          // HEADS*HID
#define HID 64
#define LOG2E 1.4426950408889634f

// ---------------- scratch (static device globals; no allocation) ----------------
__device__ __align__(16) float g_feat[NN * FH];   // 38.4 MB
__device__ __align__(16) __nv_bfloat16 g_Ahi[NN * 128];
__device__ __align__(16) __nv_bfloat16 g_Alo[NN * 128];
#define BW_TOT (192*128 + 4*192*64)
__device__ __align__(16) __nv_bfloat16 g_Bhi5[BW_TOT];
__device__ __align__(16) __nv_bfloat16 g_Blo5[BW_TOT];
__device__ __align__(16) float4 g_el4[NN];
__device__ __align__(16) float4 g_er4[NN];
__device__ int   g_cnt[NN];
__device__ int   g_rp[NN + 1];
__device__ int   g_wp[NN];
__device__ int   g_col[NE];
__device__ int   g_bsum[64];

__device__ __forceinline__ float lrelu(float x, float s) { return x > 0.f ? x : s * x; }

// ---------------- cp.async helpers ----------------
__device__ __forceinline__ void cpasync16(uint32_t saddr, const void* gaddr, uint32_t srcbytes) {
    asm volatile("cp.async.ca.shared.global [%0], [%1], 16, %2;"
                 :: "r"(saddr), "l"(gaddr), "r"(srcbytes));
}
__device__ __forceinline__ void cp_commit() {
    asm volatile("cp.async.commit_group;");
}
template <int N>
__device__ __forceinline__ void cp_wait() {
    asm volatile("cp.async.wait_group %0;" :: "n"(N));
}

// ---------------- CSR build (runs on forked stream) ----------------
__global__ void k_zero() {
    int i = blockIdx.x * blockDim.x + threadIdx.x;
    if (i < NN) g_cnt[i] = 0;
}
__global__ void k_hist(const int* __restrict__ dst) {
    int e = blockIdx.x * blockDim.x + threadIdx.x;
    if (e < NE) atomicAdd(&g_cnt[dst[e]], 1);
}
__global__ __launch_bounds__(1024) void k_scanA() {
    __shared__ int wsum[32];
    int tid = threadIdx.x, lane = tid & 31, wid = tid >> 5;
    int i = blockIdx.x * 1024 + tid;
    int v = (i < NN) ? g_cnt[i] : 0;
    int x = v;
    #pragma unroll
    for (int o = 1; o < 32; o <<= 1) {
        int t = __shfl_up_sync(0xffffffffu, x, o);
        if (lane >= o) x += t;
    }
    if (lane == 31) wsum[wid] = x;
    __syncthreads();
    if (wid == 0) {
        int y = wsum[lane];
        #pragma unroll
        for (int o = 1; o < 32; o <<= 1) {
            int t = __shfl_up_sync(0xffffffffu, y, o);
            if (lane >= o) y += t;
        }
        wsum[lane] = y;
    }
    __syncthreads();
    int pre = (wid ? wsum[wid - 1] : 0) + x - v;
    if (i < NN) g_rp[i] = pre;
    if (tid == 1023) g_bsum[blockIdx.x] = pre + v;
}
__global__ __launch_bounds__(1024) void k_scanB(int nblk) {
    __shared__ int sb[64];
    int tid = threadIdx.x;
    if (tid < nblk) sb[tid] = g_bsum[tid];
    __syncthreads();
    int off = 0;
    for (int j = 0; j < (int)blockIdx.x; j++) off += sb[j];
    int i = blockIdx.x * 1024 + tid;
    if (i < NN) {
        int v = g_rp[i] + off;
        g_rp[i] = v;
        g_wp[i] = v;
    }
    if (blockIdx.x == gridDim.x - 1 && tid == 0) {
        int tot = 0;
        for (int j = 0; j < nblk; j++) tot += sb[j];
        g_rp[NN] = tot;
    }
}
__global__ void k_scatter(const int* __restrict__ src, const int* __restrict__ dst) {
    int e = blockIdx.x * blockDim.x + threadIdx.x;
    if (e < NE) {
        int p = atomicAdd(&g_wp[dst[e]], 1);
        g_col[p] = src[e];
    }
}

// ---------------- prep: split all weights + split input (main stream) ----------------
__global__ void k_prep(const float* __restrict__ x,
                       const float* __restrict__ W0, const float* __restrict__ W1,
                       const float* __restrict__ W2, const float* __restrict__ W3,
                       const float* __restrict__ W4) {
    int i = blockIdx.x * blockDim.x + threadIdx.x;
    if (i < BW_TOT) {
        int l, j, K, off;
        if (i < 192 * 128) { l = 0; j = i; K = 128; off = 0; }
        else {
            int r = i - 192 * 128;
            l = 1 + r / (192 * 64);
            j = r % (192 * 64);
            K = 64;
            off = 192 * 128 + (l - 1) * 192 * 64;
        }
        const float* W = (l == 0) ? W0 : (l == 1) ? W1 : (l == 2) ? W2 : (l == 3) ? W3 : W4;
        int k = j / FH, n = j % FH;
        float v = W[j];
        __nv_bfloat16 h = __float2bfloat16(v);
        g_Bhi5[off + n * K + k] = h;
        g_Blo5[off + n * K + k] = __float2bfloat16(v - __bfloat162float(h));
    }
    if (i < NN * 128) {
        float v = x[i];
        __nv_bfloat16 h = __float2bfloat16(v);
        g_Ahi[i] = h;
        g_Alo[i] = __float2bfloat16(v - __bfloat162float(h));
    }
}

// ---------------- mma.sync bf16 split GEMM, 512 threads, 128x192 tile,
// two-stage cp.async double buffer + fused attention-logit epilogue ----------------
__device__ __forceinline__ void mma16816(float* d, const uint32_t* a, const uint32_t* b) {
    asm volatile("mma.sync.aligned.m16n8k16.row.col.f32.bf16.bf16.f32 "
        "{%0,%1,%2,%3}, {%4,%5,%6,%7}, {%8,%9}, {%0,%1,%2,%3};"
        : "+f"(d[0]), "+f"(d[1]), "+f"(d[2]), "+f"(d[3])
        : "r"(a[0]), "r"(a[1]), "r"(a[2]), "r"(a[3]), "r"(b[0]), "r"(b[1]));
}
#define ASTR 24
#define SM_A_ELE 3072
#define SM_B_ELE 4608
#define SM_B_OFF 12288
#define SM_EL_OFF ((12288 + 18432) * 2)
#define SM_TOTAL (SM_EL_OFF + 2 * 1536 * 4)

template <int K>
__global__ __launch_bounds__(512, 1) void k_gemm_mma(int boff, const float* __restrict__ al,
                                                     const float* __restrict__ ar) {
    extern __shared__ __nv_bfloat16 smem[];
    __nv_bfloat16* sA = smem;
    __nv_bfloat16* sB = smem + SM_B_OFF;
    float* s_el = (float*)((char*)smem + SM_EL_OFF);
    float* s_er = s_el + 1536;
    const int NT = K / 16;

    int tid = threadIdx.x, lane = tid & 31, w = tid >> 5;
    int mw = w & 3, nw = w >> 2;
    int m0 = blockIdx.x * 128;
    int g = lane >> 2, t = lane & 3;

    int halfA = tid >> 8, jA = tid & 255, rA = jA >> 1, pA = jA & 1;
    const __nv_bfloat16* gA = (halfA ? g_Alo : g_Ahi) + (size_t)(m0 + rA) * K + pA * 8;
    uint32_t okA = (m0 + rA < NN) ? 16u : 0u;
    uint32_t sAb = (uint32_t)__cvta_generic_to_shared(sA);
    uint32_t dstA0 = sAb + (uint32_t)(halfA * SM_A_ELE + rA * ASTR + pA * 8) * 2;
    int half0 = tid / 384, j0 = tid % 384, r0 = j0 >> 1, p0 = j0 & 1;
    const __nv_bfloat16* gB0 = (half0 ? g_Blo5 : g_Bhi5) + boff + r0 * K + p0 * 8;
    uint32_t sBb = (uint32_t)__cvta_generic_to_shared(sB);
    uint32_t dstB00 = sBb + (uint32_t)(half0 * SM_B_ELE + r0 * ASTR + p0 * 8) * 2;
    int j1 = tid + 128, r1 = j1 >> 1, p1 = j1 & 1;
    const __nv_bfloat16* gB1 = g_Blo5 + boff + r1 * K + p1 * 8;
    uint32_t dstB10 = sBb + (uint32_t)(SM_B_ELE + r1 * ASTR + p1 * 8) * 2;

    float d[2][6][4];
    #pragma unroll
    for (int i = 0; i < 2; i++)
        #pragma unroll
        for (int j = 0; j < 6; j++)
            #pragma unroll
            for (int q = 0; q < 4; q++) d[i][j][q] = 0.f;

    cpasync16(dstA0, gA, okA);
    cpasync16(dstB00, gB0, 16u);
    if (tid < 256) cpasync16(dstB10, gB1, 16u);
    cp_commit();

    #pragma unroll
    for (int kt = 0; kt < NT; kt++) {
        int buf = kt & 1;
        if (kt + 1 < NT) {
            int nbuf = (kt + 1) & 1;
            int k0 = (kt + 1) * 16;
            cpasync16(dstA0 + nbuf * (2 * SM_A_ELE * 2), gA + k0, okA);
            cpasync16(dstB00 + nbuf * (2 * SM_B_ELE * 2), gB0 + k0, 16u);
            if (tid < 256) cpasync16(dstB10 + nbuf * (2 * SM_B_ELE * 2), gB1 + k0, 16u);
            cp_commit();
            cp_wait<1>();
        } else {
            cp_wait<0>();
        }
        __syncthreads();

        const __nv_bfloat16* Abuf = sA + buf * 2 * SM_A_ELE;
        const __nv_bfloat16* Bbuf = sB + buf * 2 * SM_B_ELE;
        uint32_t afr[2][2][4];
        #pragma unroll
        for (int half = 0; half < 2; half++)
            #pragma unroll
            for (int mt = 0; mt < 2; mt++) {
                const __nv_bfloat16* base = Abuf + half * SM_A_ELE + (mw * 32 + mt * 16) * ASTR;
                afr[half][mt][0] = *(const uint32_t*)(base + g * ASTR + 2 * t);
                afr[half][mt][1] = *(const uint32_t*)(base + (g + 8) * ASTR + 2 * t);
                afr[half][mt][2] = *(const uint32_t*)(base + g * ASTR + 2 * t + 8);
                afr[half][mt][3] = *(const uint32_t*)(base + (g + 8) * ASTR + 2 * t + 8);
            }
        uint32_t bfr[2][6][2];
        #pragma unroll
        for (int half = 0; half < 2; half++)
            #pragma unroll
            for (int nt = 0; nt < 6; nt++) {
                const __nv_bfloat16* base = Bbuf + half * SM_B_ELE + (nw * 48 + nt * 8) * ASTR;
                bfr[half][nt][0] = *(const uint32_t*)(base + g * ASTR + 2 * t);
                bfr[half][nt][1] = *(const uint32_t*)(base + g * ASTR + 2 * t + 8);
            }
        #pragma unroll
        for (int mt = 0; mt < 2; mt++)
            #pragma unroll
            for (int nt = 0; nt < 6; nt++) {
                mma16816(d[mt][nt], afr[0][mt], bfr[0][nt]);
                mma16816(d[mt][nt], afr[0][mt], bfr[1][nt]);
                mma16816(d[mt][nt], afr[1][mt], bfr[0][nt]);
            }
        __syncthreads();
    }

    #pragma unroll
    for (int mt = 0; mt < 2; mt++) {
        int r0s = m0 + mw * 32 + mt * 16 + g;
        #pragma unroll
        for (int nt = 0; nt < 6; nt++) {
            int c = nw * 48 + nt * 8 + 2 * t;
            if (r0s < NN)
                *(float2*)&g_feat[(size_t)r0s * FH + c] = make_float2(d[mt][nt][0], d[mt][nt][1]);
            if (r0s + 8 < NN)
                *(float2*)&g_feat[(size_t)(r0s + 8) * FH + c] = make_float2(d[mt][nt][2], d[mt][nt][3]);
        }
    }

    int n0q = nw * 48;
    int hA = n0q >> 6, hB = (n0q + 47) >> 6;
    float pelA[2][2] = {{0.f,0.f},{0.f,0.f}}, pelB[2][2] = {{0.f,0.f},{0.f,0.f}};
    float perA[2][2] = {{0.f,0.f},{0.f,0.f}}, perB[2][2] = {{0.f,0.f},{0.f,0.f}};
    #pragma unroll
    for (int nt = 0; nt < 6; nt++) {
        int c = n0q + nt * 8 + 2 * t;
        float a0 = al[c] * LOG2E, a1 = al[c + 1] * LOG2E;
        float r0v = ar[c] * LOG2E, r1v = ar[c + 1] * LOG2E;
        bool isA = ((n0q + nt * 8) >> 6) == hA;
        #pragma unroll
        for (int mt = 0; mt < 2; mt++) {
            float el_g  = d[mt][nt][0] * a0 + d[mt][nt][1] * a1;
            float el_g8 = d[mt][nt][2] * a0 + d[mt][nt][3] * a1;
            float er_g  = d[mt][nt][0] * r0v + d[mt][nt][1] * r1v;
            float er_g8 = d[mt][nt][2] * r0v + d[mt][nt][3] * r1v;
            if (isA) { pelA[mt][0] += el_g; pelA[mt][1] += el_g8;
                       perA[mt][0] += er_g; perA[mt][1] += er_g8; }
            else     { pelB[mt][0] += el_g; pelB[mt][1] += el_g8;
                       perB[mt][0] += er_g; perB[mt][1] += er_g8; }
        }
    }
    #pragma unroll
    for (int mt = 0; mt < 2; mt++)
        #pragma unroll
        for (int gg = 0; gg < 2; gg++)
            #pragma unroll
            for (int o = 1; o <= 2; o <<= 1) {
                pelA[mt][gg] += __shfl_xor_sync(0xffffffffu, pelA[mt][gg], o);
                pelB[mt][gg] += __shfl_xor_sync(0xffffffffu, pelB[mt][gg], o);
                perA[mt][gg] += __shfl_xor_sync(0xffffffffu, perA[mt][gg], o);
                perB[mt][gg] += __shfl_xor_sync(0xffffffffu, perB[mt][gg], o);
            }
    if (t == 0) {
        #pragma unroll
        for (int mt = 0; mt < 2; mt++)
            #pragma unroll
            for (int gg = 0; gg < 2; gg++) {
                int rl = mw * 32 + mt * 16 + g + gg * 8;
                #pragma unroll
                for (int h = 0; h < 3; h++) {
                    float ve = (h == hA) ? pelA[mt][gg] : (h == hB) ? pelB[mt][gg] : 0.f;
                    float vr = (h == hA) ? perA[mt][gg] : (h == hB) ? perB[mt][gg] : 0.f;
                    s_el[(nw * 128 + rl) * 3 + h] = ve;
                    s_er[(nw * 128 + rl) * 3 + h] = vr;
                }
            }
    }
    __syncthreads();
    if (tid < 384) {
        int row = tid / 3, h = tid % 3;
        float se = s_el[row * 3 + h] + s_el[(128 + row) * 3 + h]
                 + s_el[(256 + row) * 3 + h] + s_el[(384 + row) * 3 + h];
        float sr = s_er[row * 3 + h] + s_er[(128 + row) * 3 + h]
                 + s_er[(256 + row) * 3 + h] + s_er[(384 + row) * 3 + h];
        int r = m0 + row;
        if (r < NN) {
            ((float*)&g_el4[r])[h] = se;
            ((float*)&g_er4[r])[h] = sr;
        }
    }
}

// ---------------- single-pass online-softmax aggregation ----------------
__global__ __launch_bounds__(256) void k_agg(const float* __restrict__ b,
                                             const float* __restrict__ Wo,
                                             const float* __restrict__ bo,
                                             float* __restrict__ out) {
    int w = (blockIdx.x * blockDim.x + threadIdx.x) >> 5;
    int lane = threadIdx.x & 31;
    if (w >= NN) return;
    int beg = g_rp[w], end = g_rp[w + 1];
    float4 er = g_er4[w];

    float m0 = -1e30f, m1 = -1e30f, m2 = -1e30f;
    float s0 = 0.f, s1 = 0.f, s2 = 0.f;
    float2 a0 = {0.f, 0.f}, a1 = {0.f, 0.f}, a2 = {0.f, 0.f};

    for (int e = beg; e < end; e++) {
        int s = g_col[e];
        float4 el = g_el4[s];
        float x0 = lrelu(el.x + er.x, 0.2f);
        float x1 = lrelu(el.y + er.y, 0.2f);
        float x2 = lrelu(el.z + er.z, 0.2f);
        if (x0 > m0) { float sc = exp2f(m0 - x0); s0 *= sc; a0.x *= sc; a0.y *= sc; m0 = x0; }
        if (x1 > m1) { float sc = exp2f(m1 - x1); s1 *= sc; a1.x *= sc; a1.y *= sc; m1 = x1; }
        if (x2 > m2) { float sc = exp2f(m2 - x2); s2 *= sc; a2.x *= sc; a2.y *= sc; m2 = x2; }
        float w0 = exp2f(x0 - m0), w1 = exp2f(x1 - m1), w2 = exp2f(x2 - m2);
        s0 += w0; s1 += w1; s2 += w2;
        const float2* f2 = (const float2*)(g_feat + (size_t)s * FH);
        float2 v0 = f2[lane], v1 = f2[lane + 32], v2 = f2[lane + 64];
        a0.x += w0 * v0.x; a0.y += w0 * v0.y;
        a1.x += w1 * v1.x; a1.y += w1 * v1.y;
        a2.x += w2 * v2.x; a2.y += w2 * v2.y;
    }
    float i0 = s0 > 0.f ? 1.f / s0 : 0.f;
    float i1 = s1 > 0.f ? 1.f / s1 : 0.f;
    float i2 = s2 > 0.f ? 1.f / s2 : 0.f;
    float2 b0 = *(const float2*)(b + 2 * lane);
    float2 b1 = *(const float2*)(b + 64 + 2 * lane);
    float2 b2 = *(const float2*)(b + 128 + 2 * lane);
    float v0x = lrelu(a0.x * i0 + b0.x, 0.01f), v0y = lrelu(a0.y * i0 + b0.y, 0.01f);
    float v1x = lrelu(a1.x * i1 + b1.x, 0.01f), v1y = lrelu(a1.y * i1 + b1.y, 0.01f);
    float v2x = lrelu(a2.x * i2 + b2.x, 0.01f), v2y = lrelu(a2.y * i2 + b2.y, 0.01f);
    float rx = (v0x + v1x + v2x) * (1.f / 3.f);
    float ry = (v0y + v1y + v2y) * (1.f / 3.f);

    if (Wo) {
        #pragma unroll
        for (int c = 0; c < 8; c++) {
            float v = rx * Wo[(2 * lane) * 8 + c] + ry * Wo[(2 * lane + 1) * 8 + c];
            #pragma unroll
            for (int o = 16; o; o >>= 1) v += __shfl_xor_sync(0xffffffffu, v, o);
            if (lane == 0) out[w * 8 + c] = v + bo[c];
        }
    } else {
        __nv_bfloat16 hx = __float2bfloat16(rx);
        __nv_bfloat16 hy = __float2bfloat16(ry);
        __nv_bfloat16 lx = __float2bfloat16(rx - __bfloat162float(hx));
        __nv_bfloat16 ly = __float2bfloat16(ry - __bfloat162float(hy));
        ((__nv_bfloat162*)g_Ahi)[w * 32 + lane] = __nv_bfloat162(hx, hy);
        ((__nv_bfloat162*)g_Alo)[w * 32 + lane] = __nv_bfloat162(lx, ly);
    }
}

// ---------------- launch ----------------
extern "C" void kernel_launch(void* const* d_in, const int* in_sizes, int n_in,
                              void* d_out, int out_size) {
    const float* x   = (const float*)d_in[0];
    const int*   src = (const int*)d_in[1];
    const int*   dst = (const int*)d_in[2];
    const float *W[5], *b[5], *al[5], *ar[5];
    for (int l = 0; l < 5; l++) {
        W[l]  = (const float*)d_in[3 + 4 * l];
        b[l]  = (const float*)d_in[4 + 4 * l];
        al[l] = (const float*)d_in[5 + 4 * l];
        ar[l] = (const float*)d_in[6 + 4 * l];
    }
    const float* Wo = (const float*)d_in[23];
    const float* bo = (const float*)d_in[24];
    float* out = (float*)d_out;

    cudaFuncSetAttribute(k_gemm_mma<128>, cudaFuncAttributeMaxDynamicSharedMemorySize, SM_TOTAL);
    cudaFuncSetAttribute(k_gemm_mma<64>,  cudaFuncAttributeMaxDynamicSharedMemorySize, SM_TOTAL);

    // forked capture stream for the CSR chain (independent of splits/GEMM0)
    cudaStream_t s2;
    cudaEvent_t evFork, evJoin;
    cudaStreamCreateWithFlags(&s2, cudaStreamNonBlocking);
    cudaEventCreateWithFlags(&evFork, cudaEventDisableTiming);
    cudaEventCreateWithFlags(&evJoin, cudaEventDisableTiming);

    int nblk = (NN + 1023) / 1024;
    cudaEventRecord(evFork, 0);
    cudaStreamWaitEvent(s2, evFork, 0);
    k_zero<<<(NN + 255) / 256, 256, 0, s2>>>();
    k_hist<<<(NE + 255) / 256, 256, 0, s2>>>(dst);
    k_scanA<<<nblk, 1024, 0, s2>>>();
    k_scanB<<<nblk, 1024, 0, s2>>>(nblk);
    k_scatter<<<(NE + 255) / 256, 256, 0, s2>>>(src, dst);
    cudaEventRecord(evJoin, s2);

    // main stream: splits + layer-0 GEMM run concurrently with CSR build
    k_prep<<<(NN * 128 + 255) / 256, 256>>>(x, W[0], W[1], W[2], W[3], W[4]);

    int wgrid = (NN * 32 + 255) / 256;
    int ggrid = (NN + 127) / 128;
    for (int l = 0; l < 5; l++) {
        int boff = (l == 0) ? 0 : 192 * 128 + (l - 1) * 192 * 64;
        if (l == 0) k_gemm_mma<128><<<ggrid, 512, SM_TOTAL>>>(boff, al[l], ar[l]);
        else        k_gemm_mma<64><<<ggrid, 512, SM_TOTAL>>>(boff, al[l], ar[l]);
        if (l == 0) cudaStreamWaitEvent(0, evJoin, 0);   // agg needs CSR
        if (l == 4) k_agg<<<wgrid, 256>>>(b[l], Wo, bo, out);
        else        k_agg<<<wgrid, 256>>>(b[l], nullptr, nullptr, nullptr);
    }
}